// round 12
// baseline (speedup 1.0000x reference)
#include <cuda_runtime.h>
#include <math.h>

// Problem constants
#define BB 4
#define KKK 512          // slots per batch
#define DDD 512          // slot dim
#define DPP 128          // pairwise dim
#define NH 8             // heads
#define HDIM 64          // head dim
#define MROWS (BB*KKK)   // 2048
#define BH (BB*NH)       // 32

typedef unsigned u32;
typedef unsigned long long u64;

// ---------- packed fp32x2 helpers (edge bias kernel) ----------
__device__ __forceinline__ u64 dup2f(float x){
    u64 r; unsigned xi = __float_as_uint(x);
    asm("mov.b64 %0, {%1,%1};" : "=l"(r) : "r"(xi));
    return r;
}
__device__ __forceinline__ u64 pack2f(float x, float y){
    u64 r;
    asm("mov.b64 %0, {%1,%2};" : "=l"(r) : "r"(__float_as_uint(x)), "r"(__float_as_uint(y)));
    return r;
}
__device__ __forceinline__ void unpack2f(u64 v, float &x, float &y){
    unsigned a,b;
    asm("mov.b64 {%0,%1}, %2;" : "=r"(a), "=r"(b) : "l"(v));
    x = __uint_as_float(a); y = __uint_as_float(b);
}
__device__ __forceinline__ void ffma2(u64 &d, u64 a, u64 b){
    asm("fma.rn.f32x2 %0, %1, %2, %0;" : "+l"(d) : "l"(a), "l"(b));
}

// ---------- tf32 MMA helpers ----------
__device__ __forceinline__ float to_tf32(float x){
    float r; asm("cvt.rna.tf32.f32 %0, %1;" : "=f"(r) : "f"(x)); return r;
}
__device__ __forceinline__ float4 cvt4(float4 v){
    v.x = to_tf32(v.x); v.y = to_tf32(v.y);
    v.z = to_tf32(v.z); v.w = to_tf32(v.w);
    return v;
}
__device__ __forceinline__ void mma8(float* c, const u32* a, const u32* b){
    asm("mma.sync.aligned.m16n8k8.row.col.f32.tf32.tf32.f32 "
        "{%0,%1,%2,%3}, {%4,%5,%6,%7}, {%8,%9}, {%0,%1,%2,%3};"
        : "+f"(c[0]), "+f"(c[1]), "+f"(c[2]), "+f"(c[3])
        : "r"(a[0]), "r"(a[1]), "r"(a[2]), "r"(a[3]),
          "r"(b[0]), "r"(b[1]));
}

// ---------- scratch (no dynamic allocation allowed) ----------
__device__ float g_x[MROWS*DDD];
__device__ float g_qkv[MROWS*3*DDD];
__device__ float g_logits[(size_t)BH*KKK*KKK];   // 33.5 MB
__device__ float g_attnout[MROWS*DDD];
__device__ float g_slots2[MROWS*DDD];
__device__ float g_ffn[MROWS*4*DDD];

// =====================================================================
// mma_core: C(128 x BN) += A(128 x Ktot) * B(Ktot x BN), tf32 tensor path
//   A row-major (lda), staged to As[m][20]        (stride 20, conflict-free)
//   B:
//     BNK=false: global row-major K x N (weights)  -> Bs[k][BN+8]
//     BNK=true : global row-major N x K (K-slots)  -> Bs[n][20] (no transpose)
//   256 threads = 8 warps (4 m-rows x 2 n-cols), warp tile 32 x (BN/2).
//   Register-prefetch pipeline over single smem buffer.
// =====================================================================
template<int BN, bool BNK>
__device__ __forceinline__ void mma_core(
    const float* __restrict__ A, int lda,
    const float* __restrict__ B, int ldb,
    int Ktot, float* smem, float (&acc)[2][BN/16][4])
{
    constexpr int NF = BN/16;
    constexpr int SB = BN + 8;       // 136 or 72; both ≡ 8 (mod 32)
    constexpr int BITER = BN/64;     // B-loader iterations (2 or 1)
    float* As = smem;                // 128*20 floats
    float* Bs = smem + 128*20;

    const int tid  = threadIdx.x;
    const int warp = tid >> 5, lane = tid & 31;
    const int wr = warp & 3, wc = warp >> 2;
    const int g = lane >> 2, t = lane & 3;
    const int mw = wr * 32, nw = wc * (BN/2);

    // A loader mapping: 128x16 tile, 512 float4, 2 per thread
    const int ar0 = tid >> 2,  ac0 = (tid & 3) * 4;
    const int ar1 = (tid+256) >> 2, ac1 = ((tid+256) & 3) * 4;

    float4 pa0, pa1, pb0, pb1;

    // prologue: fetch tile 0
    pa0 = cvt4(*(const float4*)(A + (size_t)ar0*lda + ac0));
    pa1 = cvt4(*(const float4*)(A + (size_t)ar1*lda + ac1));
    if (BNK){
        pb0 = cvt4(*(const float4*)(B + (size_t)ar0*ldb + ac0));
        if (BITER == 2)
            pb1 = cvt4(*(const float4*)(B + (size_t)ar1*ldb + ac1));
    } else {
        const int br = tid / (BN/4), bc = (tid % (BN/4)) * 4;
        pb0 = cvt4(*(const float4*)(B + (size_t)br*ldb + bc));
        if (BITER == 2){
            const int br2 = (tid+256) / (BN/4), bc2 = ((tid+256) % (BN/4)) * 4;
            pb1 = cvt4(*(const float4*)(B + (size_t)br2*ldb + bc2));
        }
    }
    // store tile 0
    *(float4*)(As + ar0*20 + ac0) = pa0;
    *(float4*)(As + ar1*20 + ac1) = pa1;
    if (BNK){
        *(float4*)(Bs + ar0*20 + ac0) = pb0;
        if (BITER == 2) *(float4*)(Bs + ar1*20 + ac1) = pb1;
    } else {
        const int br = tid / (BN/4), bc = (tid % (BN/4)) * 4;
        *(float4*)(Bs + br*SB + bc) = pb0;
        if (BITER == 2){
            const int br2 = (tid+256) / (BN/4), bc2 = ((tid+256) % (BN/4)) * 4;
            *(float4*)(Bs + br2*SB + bc2) = pb1;
        }
    }
    __syncthreads();

    for (int k0 = 0; k0 < Ktot; k0 += 16){
        const bool notlast = (k0 + 16 < Ktot);
        // prefetch next tile into registers
        if (notlast){
            const int kn = k0 + 16;
            pa0 = cvt4(*(const float4*)(A + (size_t)ar0*lda + kn + ac0));
            pa1 = cvt4(*(const float4*)(A + (size_t)ar1*lda + kn + ac1));
            if (BNK){
                pb0 = cvt4(*(const float4*)(B + (size_t)ar0*ldb + kn + ac0));
                if (BITER == 2)
                    pb1 = cvt4(*(const float4*)(B + (size_t)ar1*ldb + kn + ac1));
            } else {
                const int br = tid / (BN/4), bc = (tid % (BN/4)) * 4;
                pb0 = cvt4(*(const float4*)(B + (size_t)(kn+br)*ldb + bc));
                if (BITER == 2){
                    const int br2 = (tid+256) / (BN/4), bc2 = ((tid+256) % (BN/4)) * 4;
                    pb1 = cvt4(*(const float4*)(B + (size_t)(kn+br2)*ldb + bc2));
                }
            }
        }
        // compute on current smem tile
        #pragma unroll
        for (int ks = 0; ks < 2; ks++){
            const int kk = ks * 8;
            u32 af[2][4];
            #pragma unroll
            for (int mf = 0; mf < 2; mf++){
                const int mb = mw + mf*16;
                af[mf][0] = __float_as_uint(As[(mb+g)*20   + kk + t]);
                af[mf][1] = __float_as_uint(As[(mb+8+g)*20 + kk + t]);
                af[mf][2] = __float_as_uint(As[(mb+g)*20   + kk + 4 + t]);
                af[mf][3] = __float_as_uint(As[(mb+8+g)*20 + kk + 4 + t]);
            }
            u32 bf[NF][2];
            #pragma unroll
            for (int nf = 0; nf < NF; nf++){
                const int nb = nw + nf*8;
                if (BNK){
                    bf[nf][0] = __float_as_uint(Bs[(nb+g)*20 + kk + t]);
                    bf[nf][1] = __float_as_uint(Bs[(nb+g)*20 + kk + 4 + t]);
                } else {
                    bf[nf][0] = __float_as_uint(Bs[(kk+t)*SB   + nb + g]);
                    bf[nf][1] = __float_as_uint(Bs[(kk+4+t)*SB + nb + g]);
                }
            }
            #pragma unroll
            for (int mf = 0; mf < 2; mf++)
                #pragma unroll
                for (int nf = 0; nf < NF; nf++)
                    mma8(acc[mf][nf], af[mf], bf[nf]);
        }
        __syncthreads();
        if (notlast){
            *(float4*)(As + ar0*20 + ac0) = pa0;
            *(float4*)(As + ar1*20 + ac1) = pa1;
            if (BNK){
                *(float4*)(Bs + ar0*20 + ac0) = pb0;
                if (BITER == 2) *(float4*)(Bs + ar1*20 + ac1) = pb1;
            } else {
                const int br = tid / (BN/4), bc = (tid % (BN/4)) * 4;
                *(float4*)(Bs + br*SB + bc) = pb0;
                if (BITER == 2){
                    const int br2 = (tid+256) / (BN/4), bc2 = ((tid+256) % (BN/4)) * 4;
                    *(float4*)(Bs + br2*SB + bc2) = pb1;
                }
            }
            __syncthreads();
        }
    }
}

// ---------- projection GEMM + fused epilogues ----------
// EPI: 0 = none, 1 = +bias then exact GELU, 2 = +bias then +residual
template<int BN, int EPI>
__global__ void __launch_bounds__(256) mma_proj(
    const float* __restrict__ A, const float* __restrict__ Bw,
    const float* __restrict__ bias, const float* __restrict__ Res,
    float* __restrict__ C, int lda, int N, int Ktot)
{
    __shared__ float smem[128*20 + 16*(BN+8)];
    const float* Ab = A  + (size_t)blockIdx.y*128*lda;
    const float* Bb = Bw + blockIdx.x*BN;
    float acc[2][BN/16][4] = {};
    mma_core<BN,false>(Ab, lda, Bb, N, Ktot, smem, acc);

    const int tid  = threadIdx.x;
    const int warp = tid >> 5, lane = tid & 31;
    const int wr = warp & 3, wc = warp >> 2;
    const int g = lane >> 2, t = lane & 3;
    const size_t row0 = (size_t)blockIdx.y*128 + wr*32;
    const int col0 = blockIdx.x*BN + wc*(BN/2);

    #pragma unroll
    for (int mf = 0; mf < 2; mf++){
        #pragma unroll
        for (int nf = 0; nf < BN/16; nf++){
            const int col = col0 + nf*8 + t*2;
            float b0 = 0.f, b1 = 0.f;
            if (EPI != 0){ b0 = bias[col]; b1 = bias[col+1]; }
            #pragma unroll
            for (int half = 0; half < 2; half++){
                const size_t r = row0 + mf*16 + g + half*8;
                float v0 = acc[mf][nf][half*2]   + b0;
                float v1 = acc[mf][nf][half*2+1] + b1;
                if (EPI == 1){
                    v0 = 0.5f*v0*(1.0f + erff(v0*0.70710678118654752f));
                    v1 = 0.5f*v1*(1.0f + erff(v1*0.70710678118654752f));
                }
                if (EPI == 2){
                    float2 rr = *(const float2*)(Res + r*(size_t)N + col);
                    v0 += rr.x; v1 += rr.y;
                }
                *(float2*)(C + r*(size_t)N + col) = make_float2(v0, v1);
            }
        }
    }
}

// ---------- QK^T via tensor cores: logits += 0.125 * Q K^T ----------
__global__ void __launch_bounds__(256) mma_qk(
    const float* __restrict__ qkv, float* __restrict__ logits)
{
    __shared__ float smem[128*20 + 128*20];
    const int z = blockIdx.z, b = z >> 3, h = z & 7;
    const float* Aq = qkv + ((size_t)(b*KKK) + blockIdx.y*128)*(3*DDD) + h*HDIM;
    const float* Bk = qkv + ((size_t)(b*KKK) + blockIdx.x*128)*(3*DDD) + DDD + h*HDIM;
    float acc[2][8][4] = {};
    mma_core<128,true>(Aq, 3*DDD, Bk, 3*DDD, HDIM, smem, acc);

    float* Cb = logits + ((size_t)z*KKK + blockIdx.y*128)*KKK + blockIdx.x*128;
    const int tid  = threadIdx.x;
    const int warp = tid >> 5, lane = tid & 31;
    const int wr = warp & 3, wc = warp >> 2;
    const int g = lane >> 2, t = lane & 3;
    const int r0 = wr*32, c0 = wc*64;

    #pragma unroll
    for (int mf = 0; mf < 2; mf++){
        #pragma unroll
        for (int nf = 0; nf < 8; nf++){
            const int col = c0 + nf*8 + t*2;
            #pragma unroll
            for (int half = 0; half < 2; half++){
                const int r = r0 + mf*16 + g + half*8;
                float2* p = (float2*)(Cb + (size_t)r*KKK + col);
                float2 o = *p;
                o.x += 0.125f*acc[mf][nf][half*2];
                o.y += 0.125f*acc[mf][nf][half*2+1];
                *p = o;
            }
        }
    }
}

// ---------- AV via tensor cores: out[b,q,h*64+d] = P @ V ----------
__global__ void __launch_bounds__(256) mma_av(
    const float* __restrict__ logits, const float* __restrict__ qkv,
    float* __restrict__ out)
{
    __shared__ float smem[128*20 + 16*72];
    const int z = blockIdx.z, b = z >> 3, h = z & 7;
    const float* Ap = logits + ((size_t)z*KKK + blockIdx.y*128)*KKK;
    const float* Bv = qkv + (size_t)(b*KKK)*(3*DDD) + 2*DDD + h*HDIM;
    float acc[2][4][4] = {};
    mma_core<64,false>(Ap, KKK, Bv, 3*DDD, KKK, smem, acc);

    float* Cb = out + ((size_t)(b*KKK) + blockIdx.y*128)*DDD + h*HDIM;
    const int tid  = threadIdx.x;
    const int warp = tid >> 5, lane = tid & 31;
    const int wr = warp & 3, wc = warp >> 2;
    const int g = lane >> 2, t = lane & 3;
    const int r0 = wr*32, c0 = wc*32;

    #pragma unroll
    for (int mf = 0; mf < 2; mf++){
        #pragma unroll
        for (int nf = 0; nf < 4; nf++){
            const int col = c0 + nf*8 + t*2;
            #pragma unroll
            for (int half = 0; half < 2; half++){
                const int r = r0 + mf*16 + g + half*8;
                *(float2*)(Cb + (size_t)r*DDD + col) =
                    make_float2(acc[mf][nf][half*2], acc[mf][nf][half*2+1]);
            }
        }
    }
}

// ---------- LayerNorm: one block per row (512 elems) ----------
__global__ void __launch_bounds__(128) ln_kernel(
    const float* __restrict__ in, const float* __restrict__ w,
    const float* __restrict__ b, float* __restrict__ out)
{
    const int row = blockIdx.x;
    const int t = threadIdx.x;  // 128
    float4 v = ((const float4*)(in + (size_t)row*DDD))[t];
    float s  = v.x+v.y+v.z+v.w;
    float ss = v.x*v.x+v.y*v.y+v.z*v.z+v.w*v.w;
    #pragma unroll
    for (int o=16;o>0;o>>=1){
        s  += __shfl_xor_sync(0xffffffffu, s,  o);
        ss += __shfl_xor_sync(0xffffffffu, ss, o);
    }
    __shared__ float sm[8];
    const int wid = t>>5, lid = t&31;
    if (lid==0){ sm[wid]=s; sm[4+wid]=ss; }
    __syncthreads();
    s  = sm[0]+sm[1]+sm[2]+sm[3];
    ss = sm[4]+sm[5]+sm[6]+sm[7];
    const float mean = s*(1.0f/DDD);
    const float var  = ss*(1.0f/DDD) - mean*mean;
    const float inv  = rsqrtf(var + 1e-5f);
    float4 wv = ((const float4*)w)[t];
    float4 bv = ((const float4*)b)[t];
    float4 o4;
    o4.x = (v.x-mean)*inv*wv.x + bv.x;
    o4.y = (v.y-mean)*inv*wv.y + bv.y;
    o4.z = (v.z-mean)*inv*wv.z + bv.z;
    o4.w = (v.w-mean)*inv*wv.w + bv.w;
    ((float4*)(out + (size_t)row*DDD))[t] = o4;
}

// ---------- Edge bias (HBM-bound): logits = edge_b + pairwise @ edge_w ----------
__global__ void __launch_bounds__(128) edge_bias_kernel(
    const float* __restrict__ pw, const float* __restrict__ ew,
    const float* __restrict__ eb, float* __restrict__ logits)
{
    __shared__ float ews[DPP*NH];  // [d][h]
    const int q = blockIdx.x;
    const int b = blockIdx.y;
    const int tid = threadIdx.x;   // 128
    ((float4*)ews)[tid]       = ((const float4*)ew)[tid];
    ((float4*)ews)[tid + 128] = ((const float4*)ew)[tid + 128];
    __syncthreads();

    const int k0 = tid*4;
    const float* base = pw + (((size_t)b*KKK + q)*KKK + k0)*DPP;

    u64 acc[4][4];   // [k-sub][head-pair]
    #pragma unroll
    for (int j=0;j<4;j++){
        u64 ini = pack2f(eb[2*j], eb[2*j+1]);
        #pragma unroll
        for (int g=0;g<4;g++) acc[g][j] = ini;
    }

    #pragma unroll 4
    for (int d4=0; d4<32; d4++){
        float4 p[4];
        #pragma unroll
        for (int g=0;g<4;g++)
            p[g] = *(const float4*)(base + (size_t)g*DPP + d4*4);
        #pragma unroll
        for (int x=0;x<4;x++){
            const int d = d4*4 + x;
            const u64* e2 = (const u64*)&ews[d*NH];
            u64 e0=e2[0], e1=e2[1], e2v=e2[2], e3=e2[3];
            #pragma unroll
            for (int g=0;g<4;g++){
                const float pv = (x==0)?p[g].x : (x==1)?p[g].y : (x==2)?p[g].z : p[g].w;
                u64 pd = dup2f(pv);
                ffma2(acc[g][0], pd, e0);
                ffma2(acc[g][1], pd, e1);
                ffma2(acc[g][2], pd, e2v);
                ffma2(acc[g][3], pd, e3);
            }
        }
    }

    #pragma unroll
    for (int j=0;j<4;j++){
        float x0,y0,x1,y1,x2,y2,x3,y3;
        unpack2f(acc[0][j],x0,y0); unpack2f(acc[1][j],x1,y1);
        unpack2f(acc[2][j],x2,y2); unpack2f(acc[3][j],x3,y3);
        const size_t b0 = (((size_t)(b*NH + 2*j  )*KKK + q)*KKK) + k0;
        const size_t b1 = (((size_t)(b*NH + 2*j+1)*KKK + q)*KKK) + k0;
        *(float4*)(logits + b0) = make_float4(x0,x1,x2,x3);
        *(float4*)(logits + b1) = make_float4(y0,y1,y2,y3);
    }
}

// ---------- Softmax over last dim (512) ----------
__global__ void __launch_bounds__(128) softmax_kernel(float* __restrict__ logits)
{
    const size_t row = blockIdx.x;
    float* p = logits + row*KKK;
    const int t = threadIdx.x;
    float4 v = ((float4*)p)[t];
    float m = fmaxf(fmaxf(v.x,v.y), fmaxf(v.z,v.w));
    #pragma unroll
    for (int o=16;o>0;o>>=1) m = fmaxf(m, __shfl_xor_sync(0xffffffffu,m,o));
    __shared__ float smx[4], sms[4];
    const int wid=t>>5, lid=t&31;
    if (lid==0) smx[wid]=m;
    __syncthreads();
    m = fmaxf(fmaxf(smx[0],smx[1]), fmaxf(smx[2],smx[3]));
    v.x = expf(v.x-m); v.y = expf(v.y-m); v.z = expf(v.z-m); v.w = expf(v.w-m);
    float s = v.x+v.y+v.z+v.w;
    #pragma unroll
    for (int o=16;o>0;o>>=1) s += __shfl_xor_sync(0xffffffffu,s,o);
    if (lid==0) sms[wid]=s;
    __syncthreads();
    s = sms[0]+sms[1]+sms[2]+sms[3];
    const float r = 1.0f/s;
    v.x*=r; v.y*=r; v.z*=r; v.w*=r;
    ((float4*)p)[t] = v;
}

// ---------- host launch ----------
extern "C" void kernel_launch(void* const* d_in, const int* in_sizes, int n_in,
                              void* d_out, int out_size)
{
    const float* slots    = (const float*)d_in[0];
    const float* pairwise = (const float*)d_in[1];
    const float* ln1w     = (const float*)d_in[2];
    const float* ln1b     = (const float*)d_in[3];
    const float* ln2w     = (const float*)d_in[4];
    const float* ln2b     = (const float*)d_in[5];
    const float* wqkv     = (const float*)d_in[6];
    const float* edge_w   = (const float*)d_in[7];
    const float* edge_b   = (const float*)d_in[8];
    const float* out_w    = (const float*)d_in[9];
    const float* out_b    = (const float*)d_in[10];
    const float* ffn_w1   = (const float*)d_in[11];
    const float* ffn_b1   = (const float*)d_in[12];
    const float* ffn_w2   = (const float*)d_in[13];
    const float* ffn_b2   = (const float*)d_in[14];
    float* out = (float*)d_out;

    float *x_, *qkv_, *log_, *ao_, *s2_, *ffn_;
    cudaGetSymbolAddress((void**)&x_,   g_x);
    cudaGetSymbolAddress((void**)&qkv_, g_qkv);
    cudaGetSymbolAddress((void**)&log_, g_logits);
    cudaGetSymbolAddress((void**)&ao_,  g_attnout);
    cudaGetSymbolAddress((void**)&s2_,  g_slots2);
    cudaGetSymbolAddress((void**)&ffn_, g_ffn);

    // 1) LN1
    ln_kernel<<<MROWS,128>>>(slots, ln1w, ln1b, x_);
    // 2) QKV projection (2048 x 1536 x 512), tf32 tensor cores
    mma_proj<128,0><<<dim3(3*DDD/128, MROWS/128), 256>>>(
        x_, wqkv, nullptr, nullptr, qkv_, DDD, 3*DDD, DDD);
    // 3) edge bias -> logits
    edge_bias_kernel<<<dim3(KKK,BB),128>>>(pairwise, edge_w, edge_b, log_);
    // 4) logits += 0.125 * QK^T  (tensor cores)
    mma_qk<<<dim3(KKK/128, KKK/128, BH), 256>>>(qkv_, log_);
    // 5) softmax
    softmax_kernel<<<BH*KKK,128>>>(log_);
    // 6) attn @ V -> (B,K,D)  (tensor cores)
    mma_av<<<dim3(1, KKK/128, BH), 256>>>(log_, qkv_, ao_);
    // 7) out projection + residual (2048 x 512 x 512)
    mma_proj<64,2><<<dim3(DDD/64, MROWS/128), 256>>>(
        ao_, out_w, out_b, slots, s2_, DDD, DDD, DDD);
    // 8) LN2
    ln_kernel<<<MROWS,128>>>(s2_, ln2w, ln2b, x_);
    // 9) FFN1 + exact GELU (2048 x 2048 x 512)
    mma_proj<128,1><<<dim3(4*DDD/128, MROWS/128), 256>>>(
        x_, ffn_w1, ffn_b1, nullptr, ffn_, DDD, 4*DDD, DDD);
    // 10) FFN2 + residual (2048 x 512 x 2048) -> final output
    mma_proj<64,2><<<dim3(DDD/64, MROWS/128), 256>>>(
        ffn_, ffn_w2, ffn_b2, s2_, out, 4*DDD, DDD, 4*DDD);
}

// round 13
// speedup vs baseline: 1.0082x; 1.0082x over previous
#include <cuda_runtime.h>
#include <math.h>

// Problem constants
#define BB 4
#define KKK 512          // slots per batch
#define DDD 512          // slot dim
#define DPP 128          // pairwise dim
#define NH 8             // heads
#define HDIM 64          // head dim
#define MROWS (BB*KKK)   // 2048
#define BH (BB*NH)       // 32

typedef unsigned u32;
typedef unsigned long long u64;

// ---------- packed fp32x2 helpers (edge bias kernel) ----------
__device__ __forceinline__ u64 dup2f(float x){
    u64 r; unsigned xi = __float_as_uint(x);
    asm("mov.b64 %0, {%1,%1};" : "=l"(r) : "r"(xi));
    return r;
}
__device__ __forceinline__ u64 pack2f(float x, float y){
    u64 r;
    asm("mov.b64 %0, {%1,%2};" : "=l"(r) : "r"(__float_as_uint(x)), "r"(__float_as_uint(y)));
    return r;
}
__device__ __forceinline__ void unpack2f(u64 v, float &x, float &y){
    unsigned a,b;
    asm("mov.b64 {%0,%1}, %2;" : "=r"(a), "=r"(b) : "l"(v));
    x = __uint_as_float(a); y = __uint_as_float(b);
}
__device__ __forceinline__ void ffma2(u64 &d, u64 a, u64 b){
    asm("fma.rn.f32x2 %0, %1, %2, %0;" : "+l"(d) : "l"(a), "l"(b));
}

// ---------- tf32 MMA helpers ----------
__device__ __forceinline__ float to_tf32(float x){
    float r; asm("cvt.rna.tf32.f32 %0, %1;" : "=f"(r) : "f"(x)); return r;
}
__device__ __forceinline__ float4 cvt4(float4 v){
    v.x = to_tf32(v.x); v.y = to_tf32(v.y);
    v.z = to_tf32(v.z); v.w = to_tf32(v.w);
    return v;
}
__device__ __forceinline__ void mma8(float* c, const u32* a, const u32* b){
    asm("mma.sync.aligned.m16n8k8.row.col.f32.tf32.tf32.f32 "
        "{%0,%1,%2,%3}, {%4,%5,%6,%7}, {%8,%9}, {%0,%1,%2,%3};"
        : "+f"(c[0]), "+f"(c[1]), "+f"(c[2]), "+f"(c[3])
        : "r"(a[0]), "r"(a[1]), "r"(a[2]), "r"(a[3]),
          "r"(b[0]), "r"(b[1]));
}

// ---------- scratch (no dynamic allocation allowed) ----------
__device__ float g_x[MROWS*DDD];
__device__ float g_qkv[MROWS*3*DDD];
__device__ float g_logits[(size_t)BH*KKK*KKK];   // 33.5 MB
__device__ float g_attnout[MROWS*DDD];
__device__ float g_slots2[MROWS*DDD];
__device__ float g_ffn[MROWS*4*DDD];

// =====================================================================
// mma_core: C(128 x BN) += A(128 x Ktot) * B(Ktot x BN), tf32 tensor path
//   A row-major (lda), staged to As[m][20]        (stride 20, conflict-free)
//   B:
//     BNK=false: global row-major K x N (weights)  -> Bs[k][BN+8]
//     BNK=true : global row-major N x K (K-slots)  -> Bs[n][20] (no transpose)
//   256 threads = 8 warps (4 m-rows x 2 n-cols), warp tile 32 x (BN/2).
//   Register-prefetch pipeline over single smem buffer.
// =====================================================================
template<int BN, bool BNK>
__device__ __forceinline__ void mma_core(
    const float* __restrict__ A, int lda,
    const float* __restrict__ B, int ldb,
    int Ktot, float* smem, float (&acc)[2][BN/16][4])
{
    constexpr int NF = BN/16;
    constexpr int SB = BN + 8;       // 136 or 72; both ≡ 8 (mod 32)
    constexpr int BITER = BN/64;     // B-loader iterations (2 or 1)
    float* As = smem;                // 128*20 floats
    float* Bs = smem + 128*20;

    const int tid  = threadIdx.x;
    const int warp = tid >> 5, lane = tid & 31;
    const int wr = warp & 3, wc = warp >> 2;
    const int g = lane >> 2, t = lane & 3;
    const int mw = wr * 32, nw = wc * (BN/2);

    // A loader mapping: 128x16 tile, 512 float4, 2 per thread
    const int ar0 = tid >> 2,  ac0 = (tid & 3) * 4;
    const int ar1 = (tid+256) >> 2, ac1 = ((tid+256) & 3) * 4;

    float4 pa0, pa1, pb0, pb1;

    // prologue: fetch tile 0
    pa0 = cvt4(*(const float4*)(A + (size_t)ar0*lda + ac0));
    pa1 = cvt4(*(const float4*)(A + (size_t)ar1*lda + ac1));
    if (BNK){
        pb0 = cvt4(*(const float4*)(B + (size_t)ar0*ldb + ac0));
        if (BITER == 2)
            pb1 = cvt4(*(const float4*)(B + (size_t)ar1*ldb + ac1));
    } else {
        const int br = tid / (BN/4), bc = (tid % (BN/4)) * 4;
        pb0 = cvt4(*(const float4*)(B + (size_t)br*ldb + bc));
        if (BITER == 2){
            const int br2 = (tid+256) / (BN/4), bc2 = ((tid+256) % (BN/4)) * 4;
            pb1 = cvt4(*(const float4*)(B + (size_t)br2*ldb + bc2));
        }
    }
    // store tile 0
    *(float4*)(As + ar0*20 + ac0) = pa0;
    *(float4*)(As + ar1*20 + ac1) = pa1;
    if (BNK){
        *(float4*)(Bs + ar0*20 + ac0) = pb0;
        if (BITER == 2) *(float4*)(Bs + ar1*20 + ac1) = pb1;
    } else {
        const int br = tid / (BN/4), bc = (tid % (BN/4)) * 4;
        *(float4*)(Bs + br*SB + bc) = pb0;
        if (BITER == 2){
            const int br2 = (tid+256) / (BN/4), bc2 = ((tid+256) % (BN/4)) * 4;
            *(float4*)(Bs + br2*SB + bc2) = pb1;
        }
    }
    __syncthreads();

    for (int k0 = 0; k0 < Ktot; k0 += 16){
        const bool notlast = (k0 + 16 < Ktot);
        // prefetch next tile into registers
        if (notlast){
            const int kn = k0 + 16;
            pa0 = cvt4(*(const float4*)(A + (size_t)ar0*lda + kn + ac0));
            pa1 = cvt4(*(const float4*)(A + (size_t)ar1*lda + kn + ac1));
            if (BNK){
                pb0 = cvt4(*(const float4*)(B + (size_t)ar0*ldb + kn + ac0));
                if (BITER == 2)
                    pb1 = cvt4(*(const float4*)(B + (size_t)ar1*ldb + kn + ac1));
            } else {
                const int br = tid / (BN/4), bc = (tid % (BN/4)) * 4;
                pb0 = cvt4(*(const float4*)(B + (size_t)(kn+br)*ldb + bc));
                if (BITER == 2){
                    const int br2 = (tid+256) / (BN/4), bc2 = ((tid+256) % (BN/4)) * 4;
                    pb1 = cvt4(*(const float4*)(B + (size_t)(kn+br2)*ldb + bc2));
                }
            }
        }
        // compute on current smem tile
        #pragma unroll
        for (int ks = 0; ks < 2; ks++){
            const int kk = ks * 8;
            u32 af[2][4];
            #pragma unroll
            for (int mf = 0; mf < 2; mf++){
                const int mb = mw + mf*16;
                af[mf][0] = __float_as_uint(As[(mb+g)*20   + kk + t]);
                af[mf][1] = __float_as_uint(As[(mb+8+g)*20 + kk + t]);
                af[mf][2] = __float_as_uint(As[(mb+g)*20   + kk + 4 + t]);
                af[mf][3] = __float_as_uint(As[(mb+8+g)*20 + kk + 4 + t]);
            }
            u32 bf[NF][2];
            #pragma unroll
            for (int nf = 0; nf < NF; nf++){
                const int nb = nw + nf*8;
                if (BNK){
                    bf[nf][0] = __float_as_uint(Bs[(nb+g)*20 + kk + t]);
                    bf[nf][1] = __float_as_uint(Bs[(nb+g)*20 + kk + 4 + t]);
                } else {
                    bf[nf][0] = __float_as_uint(Bs[(kk+t)*SB   + nb + g]);
                    bf[nf][1] = __float_as_uint(Bs[(kk+4+t)*SB + nb + g]);
                }
            }
            #pragma unroll
            for (int mf = 0; mf < 2; mf++)
                #pragma unroll
                for (int nf = 0; nf < NF; nf++)
                    mma8(acc[mf][nf], af[mf], bf[nf]);
        }
        __syncthreads();
        if (notlast){
            *(float4*)(As + ar0*20 + ac0) = pa0;
            *(float4*)(As + ar1*20 + ac1) = pa1;
            if (BNK){
                *(float4*)(Bs + ar0*20 + ac0) = pb0;
                if (BITER == 2) *(float4*)(Bs + ar1*20 + ac1) = pb1;
            } else {
                const int br = tid / (BN/4), bc = (tid % (BN/4)) * 4;
                *(float4*)(Bs + br*SB + bc) = pb0;
                if (BITER == 2){
                    const int br2 = (tid+256) / (BN/4), bc2 = ((tid+256) % (BN/4)) * 4;
                    *(float4*)(Bs + br2*SB + bc2) = pb1;
                }
            }
            __syncthreads();
        }
    }
}

// ---------- projection GEMM + fused epilogues ----------
// EPI: 0 = none, 1 = +bias then exact GELU, 2 = +bias then +residual
template<int BN, int EPI>
__global__ void __launch_bounds__(256) mma_proj(
    const float* __restrict__ A, const float* __restrict__ Bw,
    const float* __restrict__ bias, const float* __restrict__ Res,
    float* __restrict__ C, int lda, int N, int Ktot)
{
    __shared__ float smem[128*20 + 16*(BN+8)];
    const float* Ab = A  + (size_t)blockIdx.y*128*lda;
    const float* Bb = Bw + blockIdx.x*BN;
    float acc[2][BN/16][4] = {};
    mma_core<BN,false>(Ab, lda, Bb, N, Ktot, smem, acc);

    const int tid  = threadIdx.x;
    const int warp = tid >> 5, lane = tid & 31;
    const int wr = warp & 3, wc = warp >> 2;
    const int g = lane >> 2, t = lane & 3;
    const size_t row0 = (size_t)blockIdx.y*128 + wr*32;
    const int col0 = blockIdx.x*BN + wc*(BN/2);

    #pragma unroll
    for (int mf = 0; mf < 2; mf++){
        #pragma unroll
        for (int nf = 0; nf < BN/16; nf++){
            const int col = col0 + nf*8 + t*2;
            float b0 = 0.f, b1 = 0.f;
            if (EPI != 0){ b0 = bias[col]; b1 = bias[col+1]; }
            #pragma unroll
            for (int half = 0; half < 2; half++){
                const size_t r = row0 + mf*16 + g + half*8;
                float v0 = acc[mf][nf][half*2]   + b0;
                float v1 = acc[mf][nf][half*2+1] + b1;
                if (EPI == 1){
                    v0 = 0.5f*v0*(1.0f + erff(v0*0.70710678118654752f));
                    v1 = 0.5f*v1*(1.0f + erff(v1*0.70710678118654752f));
                }
                if (EPI == 2){
                    float2 rr = *(const float2*)(Res + r*(size_t)N + col);
                    v0 += rr.x; v1 += rr.y;
                }
                *(float2*)(C + r*(size_t)N + col) = make_float2(v0, v1);
            }
        }
    }
}

// ---------- QK^T via tensor cores: logits += 0.125 * Q K^T ----------
__global__ void __launch_bounds__(256) mma_qk(
    const float* __restrict__ qkv, float* __restrict__ logits)
{
    __shared__ float smem[128*20 + 128*20];
    const int z = blockIdx.z, b = z >> 3, h = z & 7;
    const float* Aq = qkv + ((size_t)(b*KKK) + blockIdx.y*128)*(3*DDD) + h*HDIM;
    const float* Bk = qkv + ((size_t)(b*KKK) + blockIdx.x*128)*(3*DDD) + DDD + h*HDIM;
    float acc[2][8][4] = {};
    mma_core<128,true>(Aq, 3*DDD, Bk, 3*DDD, HDIM, smem, acc);

    float* Cb = logits + ((size_t)z*KKK + blockIdx.y*128)*KKK + blockIdx.x*128;
    const int tid  = threadIdx.x;
    const int warp = tid >> 5, lane = tid & 31;
    const int wr = warp & 3, wc = warp >> 2;
    const int g = lane >> 2, t = lane & 3;
    const int r0 = wr*32, c0 = wc*64;

    #pragma unroll
    for (int mf = 0; mf < 2; mf++){
        #pragma unroll
        for (int nf = 0; nf < 8; nf++){
            const int col = c0 + nf*8 + t*2;
            #pragma unroll
            for (int half = 0; half < 2; half++){
                const int r = r0 + mf*16 + g + half*8;
                float2* p = (float2*)(Cb + (size_t)r*KKK + col);
                float2 o = *p;
                o.x += 0.125f*acc[mf][nf][half*2];
                o.y += 0.125f*acc[mf][nf][half*2+1];
                *p = o;
            }
        }
    }
}

// ---------- AV via tensor cores: out[b,q,h*64+d] = P @ V ----------
__global__ void __launch_bounds__(256) mma_av(
    const float* __restrict__ logits, const float* __restrict__ qkv,
    float* __restrict__ out)
{
    __shared__ float smem[128*20 + 16*72];
    const int z = blockIdx.z, b = z >> 3, h = z & 7;
    const float* Ap = logits + ((size_t)z*KKK + blockIdx.y*128)*KKK;
    const float* Bv = qkv + (size_t)(b*KKK)*(3*DDD) + 2*DDD + h*HDIM;
    float acc[2][4][4] = {};
    mma_core<64,false>(Ap, KKK, Bv, 3*DDD, KKK, smem, acc);

    float* Cb = out + ((size_t)(b*KKK) + blockIdx.y*128)*DDD + h*HDIM;
    const int tid  = threadIdx.x;
    const int warp = tid >> 5, lane = tid & 31;
    const int wr = warp & 3, wc = warp >> 2;
    const int g = lane >> 2, t = lane & 3;
    const int r0 = wr*32, c0 = wc*32;

    #pragma unroll
    for (int mf = 0; mf < 2; mf++){
        #pragma unroll
        for (int nf = 0; nf < 4; nf++){
            const int col = c0 + nf*8 + t*2;
            #pragma unroll
            for (int half = 0; half < 2; half++){
                const int r = r0 + mf*16 + g + half*8;
                *(float2*)(Cb + (size_t)r*DDD + col) =
                    make_float2(acc[mf][nf][half*2], acc[mf][nf][half*2+1]);
            }
        }
    }
}

// ---------- LayerNorm: one block per row (512 elems) ----------
__global__ void __launch_bounds__(128) ln_kernel(
    const float* __restrict__ in, const float* __restrict__ w,
    const float* __restrict__ b, float* __restrict__ out)
{
    const int row = blockIdx.x;
    const int t = threadIdx.x;  // 128
    float4 v = ((const float4*)(in + (size_t)row*DDD))[t];
    float s  = v.x+v.y+v.z+v.w;
    float ss = v.x*v.x+v.y*v.y+v.z*v.z+v.w*v.w;
    #pragma unroll
    for (int o=16;o>0;o>>=1){
        s  += __shfl_xor_sync(0xffffffffu, s,  o);
        ss += __shfl_xor_sync(0xffffffffu, ss, o);
    }
    __shared__ float sm[8];
    const int wid = t>>5, lid = t&31;
    if (lid==0){ sm[wid]=s; sm[4+wid]=ss; }
    __syncthreads();
    s  = sm[0]+sm[1]+sm[2]+sm[3];
    ss = sm[4]+sm[5]+sm[6]+sm[7];
    const float mean = s*(1.0f/DDD);
    const float var  = ss*(1.0f/DDD) - mean*mean;
    const float inv  = rsqrtf(var + 1e-5f);
    float4 wv = ((const float4*)w)[t];
    float4 bv = ((const float4*)b)[t];
    float4 o4;
    o4.x = (v.x-mean)*inv*wv.x + bv.x;
    o4.y = (v.y-mean)*inv*wv.y + bv.y;
    o4.z = (v.z-mean)*inv*wv.z + bv.z;
    o4.w = (v.w-mean)*inv*wv.w + bv.w;
    ((float4*)(out + (size_t)row*DDD))[t] = o4;
}

// ---------- Edge bias (HBM-bound): logits = edge_b + pairwise @ edge_w ----------
__global__ void __launch_bounds__(128) edge_bias_kernel(
    const float* __restrict__ pw, const float* __restrict__ ew,
    const float* __restrict__ eb, float* __restrict__ logits)
{
    __shared__ float ews[DPP*NH];  // [d][h]
    const int q = blockIdx.x;
    const int b = blockIdx.y;
    const int tid = threadIdx.x;   // 128
    ((float4*)ews)[tid]       = ((const float4*)ew)[tid];
    ((float4*)ews)[tid + 128] = ((const float4*)ew)[tid + 128];
    __syncthreads();

    const int k0 = tid*4;
    const float* base = pw + (((size_t)b*KKK + q)*KKK + k0)*DPP;

    u64 acc[4][4];   // [k-sub][head-pair]
    #pragma unroll
    for (int j=0;j<4;j++){
        u64 ini = pack2f(eb[2*j], eb[2*j+1]);
        #pragma unroll
        for (int g=0;g<4;g++) acc[g][j] = ini;
    }

    #pragma unroll 4
    for (int d4=0; d4<32; d4++){
        float4 p[4];
        #pragma unroll
        for (int g=0;g<4;g++)
            p[g] = *(const float4*)(base + (size_t)g*DPP + d4*4);
        #pragma unroll
        for (int x=0;x<4;x++){
            const int d = d4*4 + x;
            const u64* e2 = (const u64*)&ews[d*NH];
            u64 e0=e2[0], e1=e2[1], e2v=e2[2], e3=e2[3];
            #pragma unroll
            for (int g=0;g<4;g++){
                const float pv = (x==0)?p[g].x : (x==1)?p[g].y : (x==2)?p[g].z : p[g].w;
                u64 pd = dup2f(pv);
                ffma2(acc[g][0], pd, e0);
                ffma2(acc[g][1], pd, e1);
                ffma2(acc[g][2], pd, e2v);
                ffma2(acc[g][3], pd, e3);
            }
        }
    }

    #pragma unroll
    for (int j=0;j<4;j++){
        float x0,y0,x1,y1,x2,y2,x3,y3;
        unpack2f(acc[0][j],x0,y0); unpack2f(acc[1][j],x1,y1);
        unpack2f(acc[2][j],x2,y2); unpack2f(acc[3][j],x3,y3);
        const size_t b0 = (((size_t)(b*NH + 2*j  )*KKK + q)*KKK) + k0;
        const size_t b1 = (((size_t)(b*NH + 2*j+1)*KKK + q)*KKK) + k0;
        *(float4*)(logits + b0) = make_float4(x0,x1,x2,x3);
        *(float4*)(logits + b1) = make_float4(y0,y1,y2,y3);
    }
}

// ---------- Softmax over last dim (512) ----------
__global__ void __launch_bounds__(128) softmax_kernel(float* __restrict__ logits)
{
    const size_t row = blockIdx.x;
    float* p = logits + row*KKK;
    const int t = threadIdx.x;
    float4 v = ((float4*)p)[t];
    float m = fmaxf(fmaxf(v.x,v.y), fmaxf(v.z,v.w));
    #pragma unroll
    for (int o=16;o>0;o>>=1) m = fmaxf(m, __shfl_xor_sync(0xffffffffu,m,o));
    __shared__ float smx[4], sms[4];
    const int wid=t>>5, lid=t&31;
    if (lid==0) smx[wid]=m;
    __syncthreads();
    m = fmaxf(fmaxf(smx[0],smx[1]), fmaxf(smx[2],smx[3]));
    v.x = expf(v.x-m); v.y = expf(v.y-m); v.z = expf(v.z-m); v.w = expf(v.w-m);
    float s = v.x+v.y+v.z+v.w;
    #pragma unroll
    for (int o=16;o>0;o>>=1) s += __shfl_xor_sync(0xffffffffu,s,o);
    if (lid==0) sms[wid]=s;
    __syncthreads();
    s = sms[0]+sms[1]+sms[2]+sms[3];
    const float r = 1.0f/s;
    v.x*=r; v.y*=r; v.z*=r; v.w*=r;
    ((float4*)p)[t] = v;
}

// ---------- host launch ----------
extern "C" void kernel_launch(void* const* d_in, const int* in_sizes, int n_in,
                              void* d_out, int out_size)
{
    const float* slots    = (const float*)d_in[0];
    const float* pairwise = (const float*)d_in[1];
    const float* ln1w     = (const float*)d_in[2];
    const float* ln1b     = (const float*)d_in[3];
    const float* ln2w     = (const float*)d_in[4];
    const float* ln2b     = (const float*)d_in[5];
    const float* wqkv     = (const float*)d_in[6];
    const float* edge_w   = (const float*)d_in[7];
    const float* edge_b   = (const float*)d_in[8];
    const float* out_w    = (const float*)d_in[9];
    const float* out_b    = (const float*)d_in[10];
    const float* ffn_w1   = (const float*)d_in[11];
    const float* ffn_b1   = (const float*)d_in[12];
    const float* ffn_w2   = (const float*)d_in[13];
    const float* ffn_b2   = (const float*)d_in[14];
    float* out = (float*)d_out;

    float *x_, *qkv_, *log_, *ao_, *s2_, *ffn_;
    cudaGetSymbolAddress((void**)&x_,   g_x);
    cudaGetSymbolAddress((void**)&qkv_, g_qkv);
    cudaGetSymbolAddress((void**)&log_, g_logits);
    cudaGetSymbolAddress((void**)&ao_,  g_attnout);
    cudaGetSymbolAddress((void**)&s2_,  g_slots2);
    cudaGetSymbolAddress((void**)&ffn_, g_ffn);

    // 1) LN1
    ln_kernel<<<MROWS,128>>>(slots, ln1w, ln1b, x_);
    // 2) QKV projection (2048 x 1536 x 512), tf32 tensor cores
    mma_proj<128,0><<<dim3(3*DDD/128, MROWS/128), 256>>>(
        x_, wqkv, nullptr, nullptr, qkv_, DDD, 3*DDD, DDD);
    // 3) edge bias -> logits
    edge_bias_kernel<<<dim3(KKK,BB),128>>>(pairwise, edge_w, edge_b, log_);
    // 4) logits += 0.125 * QK^T  (tensor cores)
    mma_qk<<<dim3(KKK/128, KKK/128, BH), 256>>>(qkv_, log_);
    // 5) softmax
    softmax_kernel<<<BH*KKK,128>>>(log_);
    // 6) attn @ V -> (B,K,D)  (tensor cores)
    mma_av<<<dim3(1, KKK/128, BH), 256>>>(log_, qkv_, ao_);
    // 7) out projection + residual (2048 x 512 x 512)
    mma_proj<64,2><<<dim3(DDD/64, MROWS/128), 256>>>(
        ao_, out_w, out_b, slots, s2_, DDD, DDD, DDD);
    // 8) LN2
    ln_kernel<<<MROWS,128>>>(s2_, ln2w, ln2b, x_);
    // 9) FFN1 + exact GELU (2048 x 2048 x 512)
    mma_proj<128,1><<<dim3(4*DDD/128, MROWS/128), 256>>>(
        x_, ffn_w1, ffn_b1, nullptr, ffn_, DDD, 4*DDD, DDD);
    // 10) FFN2 + residual (2048 x 512 x 2048) -> final output
    mma_proj<64,2><<<dim3(DDD/64, MROWS/128), 256>>>(
        ffn_, ffn_w2, ffn_b2, s2_, out, 4*DDD, DDD, 4*DDD);
}

// round 14
// speedup vs baseline: 1.0085x; 1.0003x over previous
#include <cuda_runtime.h>
#include <math.h>

// Problem constants
#define BB 4
#define KKK 512          // slots per batch
#define DDD 512          // slot dim
#define DPP 128          // pairwise dim
#define NH 8             // heads
#define HDIM 64          // head dim
#define MROWS (BB*KKK)   // 2048
#define BH (BB*NH)       // 32

typedef unsigned u32;
typedef unsigned long long u64;

// ---------- packed fp32x2 helpers (edge bias kernel) ----------
__device__ __forceinline__ u64 dup2f(float x){
    u64 r; unsigned xi = __float_as_uint(x);
    asm("mov.b64 %0, {%1,%1};" : "=l"(r) : "r"(xi));
    return r;
}
__device__ __forceinline__ u64 pack2f(float x, float y){
    u64 r;
    asm("mov.b64 %0, {%1,%2};" : "=l"(r) : "r"(__float_as_uint(x)), "r"(__float_as_uint(y)));
    return r;
}
__device__ __forceinline__ void unpack2f(u64 v, float &x, float &y){
    unsigned a,b;
    asm("mov.b64 {%0,%1}, %2;" : "=r"(a), "=r"(b) : "l"(v));
    x = __uint_as_float(a); y = __uint_as_float(b);
}
__device__ __forceinline__ void ffma2(u64 &d, u64 a, u64 b){
    asm("fma.rn.f32x2 %0, %1, %2, %0;" : "+l"(d) : "l"(a), "l"(b));
}

// ---------- tf32 MMA helpers ----------
__device__ __forceinline__ float to_tf32(float x){
    float r; asm("cvt.rna.tf32.f32 %0, %1;" : "=f"(r) : "f"(x)); return r;
}
__device__ __forceinline__ float4 cvt4(float4 v){
    v.x = to_tf32(v.x); v.y = to_tf32(v.y);
    v.z = to_tf32(v.z); v.w = to_tf32(v.w);
    return v;
}
__device__ __forceinline__ void mma8(float* c, const u32* a, const u32* b){
    asm("mma.sync.aligned.m16n8k8.row.col.f32.tf32.tf32.f32 "
        "{%0,%1,%2,%3}, {%4,%5,%6,%7}, {%8,%9}, {%0,%1,%2,%3};"
        : "+f"(c[0]), "+f"(c[1]), "+f"(c[2]), "+f"(c[3])
        : "r"(a[0]), "r"(a[1]), "r"(a[2]), "r"(a[3]),
          "r"(b[0]), "r"(b[1]));
}

// ---------- scratch (no dynamic allocation allowed) ----------
__device__ float g_x[MROWS*DDD];
__device__ float g_qkv[MROWS*3*DDD];
__device__ float g_logits[(size_t)BH*KKK*KKK];   // 33.5 MB
__device__ float g_attnout[MROWS*DDD];
__device__ float g_slots2[MROWS*DDD];
__device__ float g_ffn[MROWS*4*DDD];

// =====================================================================
// mma_core: C(128 x BN) += A(128 x Ktot) * B(Ktot x BN), tf32 tensor path
//   A row-major (lda), staged to As[m][20]        (stride 20, conflict-free)
//   B:
//     BNK=false: global row-major K x N (weights)  -> Bs[k][BN+8]
//     BNK=true : global row-major N x K (K-slots)  -> Bs[n][20] (no transpose)
//   256 threads = 8 warps (4 m-rows x 2 n-cols), warp tile 32 x (BN/2).
//   Register-prefetch pipeline over single smem buffer.
// =====================================================================
template<int BN, bool BNK>
__device__ __forceinline__ void mma_core(
    const float* __restrict__ A, int lda,
    const float* __restrict__ B, int ldb,
    int Ktot, float* smem, float (&acc)[2][BN/16][4])
{
    constexpr int NF = BN/16;
    constexpr int SB = BN + 8;       // 136 or 72; both ≡ 8 (mod 32)
    constexpr int BITER = BN/64;     // B-loader iterations (2 or 1)
    float* As = smem;                // 128*20 floats
    float* Bs = smem + 128*20;

    const int tid  = threadIdx.x;
    const int warp = tid >> 5, lane = tid & 31;
    const int wr = warp & 3, wc = warp >> 2;
    const int g = lane >> 2, t = lane & 3;
    const int mw = wr * 32, nw = wc * (BN/2);

    // A loader mapping: 128x16 tile, 512 float4, 2 per thread
    const int ar0 = tid >> 2,  ac0 = (tid & 3) * 4;
    const int ar1 = (tid+256) >> 2, ac1 = ((tid+256) & 3) * 4;

    float4 pa0, pa1, pb0, pb1;

    // prologue: fetch tile 0
    pa0 = cvt4(*(const float4*)(A + (size_t)ar0*lda + ac0));
    pa1 = cvt4(*(const float4*)(A + (size_t)ar1*lda + ac1));
    if (BNK){
        pb0 = cvt4(*(const float4*)(B + (size_t)ar0*ldb + ac0));
        if (BITER == 2)
            pb1 = cvt4(*(const float4*)(B + (size_t)ar1*ldb + ac1));
    } else {
        const int br = tid / (BN/4), bc = (tid % (BN/4)) * 4;
        pb0 = cvt4(*(const float4*)(B + (size_t)br*ldb + bc));
        if (BITER == 2){
            const int br2 = (tid+256) / (BN/4), bc2 = ((tid+256) % (BN/4)) * 4;
            pb1 = cvt4(*(const float4*)(B + (size_t)br2*ldb + bc2));
        }
    }
    // store tile 0
    *(float4*)(As + ar0*20 + ac0) = pa0;
    *(float4*)(As + ar1*20 + ac1) = pa1;
    if (BNK){
        *(float4*)(Bs + ar0*20 + ac0) = pb0;
        if (BITER == 2) *(float4*)(Bs + ar1*20 + ac1) = pb1;
    } else {
        const int br = tid / (BN/4), bc = (tid % (BN/4)) * 4;
        *(float4*)(Bs + br*SB + bc) = pb0;
        if (BITER == 2){
            const int br2 = (tid+256) / (BN/4), bc2 = ((tid+256) % (BN/4)) * 4;
            *(float4*)(Bs + br2*SB + bc2) = pb1;
        }
    }
    __syncthreads();

    for (int k0 = 0; k0 < Ktot; k0 += 16){
        const bool notlast = (k0 + 16 < Ktot);
        // prefetch next tile into registers
        if (notlast){
            const int kn = k0 + 16;
            pa0 = cvt4(*(const float4*)(A + (size_t)ar0*lda + kn + ac0));
            pa1 = cvt4(*(const float4*)(A + (size_t)ar1*lda + kn + ac1));
            if (BNK){
                pb0 = cvt4(*(const float4*)(B + (size_t)ar0*ldb + kn + ac0));
                if (BITER == 2)
                    pb1 = cvt4(*(const float4*)(B + (size_t)ar1*ldb + kn + ac1));
            } else {
                const int br = tid / (BN/4), bc = (tid % (BN/4)) * 4;
                pb0 = cvt4(*(const float4*)(B + (size_t)(kn+br)*ldb + bc));
                if (BITER == 2){
                    const int br2 = (tid+256) / (BN/4), bc2 = ((tid+256) % (BN/4)) * 4;
                    pb1 = cvt4(*(const float4*)(B + (size_t)(kn+br2)*ldb + bc2));
                }
            }
        }
        // compute on current smem tile
        #pragma unroll
        for (int ks = 0; ks < 2; ks++){
            const int kk = ks * 8;
            u32 af[2][4];
            #pragma unroll
            for (int mf = 0; mf < 2; mf++){
                const int mb = mw + mf*16;
                af[mf][0] = __float_as_uint(As[(mb+g)*20   + kk + t]);
                af[mf][1] = __float_as_uint(As[(mb+8+g)*20 + kk + t]);
                af[mf][2] = __float_as_uint(As[(mb+g)*20   + kk + 4 + t]);
                af[mf][3] = __float_as_uint(As[(mb+8+g)*20 + kk + 4 + t]);
            }
            u32 bf[NF][2];
            #pragma unroll
            for (int nf = 0; nf < NF; nf++){
                const int nb = nw + nf*8;
                if (BNK){
                    bf[nf][0] = __float_as_uint(Bs[(nb+g)*20 + kk + t]);
                    bf[nf][1] = __float_as_uint(Bs[(nb+g)*20 + kk + 4 + t]);
                } else {
                    bf[nf][0] = __float_as_uint(Bs[(kk+t)*SB   + nb + g]);
                    bf[nf][1] = __float_as_uint(Bs[(kk+4+t)*SB + nb + g]);
                }
            }
            #pragma unroll
            for (int mf = 0; mf < 2; mf++)
                #pragma unroll
                for (int nf = 0; nf < NF; nf++)
                    mma8(acc[mf][nf], af[mf], bf[nf]);
        }
        __syncthreads();
        if (notlast){
            *(float4*)(As + ar0*20 + ac0) = pa0;
            *(float4*)(As + ar1*20 + ac1) = pa1;
            if (BNK){
                *(float4*)(Bs + ar0*20 + ac0) = pb0;
                if (BITER == 2) *(float4*)(Bs + ar1*20 + ac1) = pb1;
            } else {
                const int br = tid / (BN/4), bc = (tid % (BN/4)) * 4;
                *(float4*)(Bs + br*SB + bc) = pb0;
                if (BITER == 2){
                    const int br2 = (tid+256) / (BN/4), bc2 = ((tid+256) % (BN/4)) * 4;
                    *(float4*)(Bs + br2*SB + bc2) = pb1;
                }
            }
            __syncthreads();
        }
    }
}

// ---------- projection GEMM + fused epilogues ----------
// EPI: 0 = none, 1 = +bias then exact GELU, 2 = +bias then +residual
template<int BN, int EPI>
__global__ void __launch_bounds__(256) mma_proj(
    const float* __restrict__ A, const float* __restrict__ Bw,
    const float* __restrict__ bias, const float* __restrict__ Res,
    float* __restrict__ C, int lda, int N, int Ktot)
{
    __shared__ float smem[128*20 + 16*(BN+8)];
    const float* Ab = A  + (size_t)blockIdx.y*128*lda;
    const float* Bb = Bw + blockIdx.x*BN;
    float acc[2][BN/16][4] = {};
    mma_core<BN,false>(Ab, lda, Bb, N, Ktot, smem, acc);

    const int tid  = threadIdx.x;
    const int warp = tid >> 5, lane = tid & 31;
    const int wr = warp & 3, wc = warp >> 2;
    const int g = lane >> 2, t = lane & 3;
    const size_t row0 = (size_t)blockIdx.y*128 + wr*32;
    const int col0 = blockIdx.x*BN + wc*(BN/2);

    #pragma unroll
    for (int mf = 0; mf < 2; mf++){
        #pragma unroll
        for (int nf = 0; nf < BN/16; nf++){
            const int col = col0 + nf*8 + t*2;
            float b0 = 0.f, b1 = 0.f;
            if (EPI != 0){ b0 = bias[col]; b1 = bias[col+1]; }
            #pragma unroll
            for (int half = 0; half < 2; half++){
                const size_t r = row0 + mf*16 + g + half*8;
                float v0 = acc[mf][nf][half*2]   + b0;
                float v1 = acc[mf][nf][half*2+1] + b1;
                if (EPI == 1){
                    v0 = 0.5f*v0*(1.0f + erff(v0*0.70710678118654752f));
                    v1 = 0.5f*v1*(1.0f + erff(v1*0.70710678118654752f));
                }
                if (EPI == 2){
                    float2 rr = *(const float2*)(Res + r*(size_t)N + col);
                    v0 += rr.x; v1 += rr.y;
                }
                *(float2*)(C + r*(size_t)N + col) = make_float2(v0, v1);
            }
        }
    }
}

// ---------- QK^T via tensor cores: logits += 0.125 * Q K^T ----------
__global__ void __launch_bounds__(256) mma_qk(
    const float* __restrict__ qkv, float* __restrict__ logits)
{
    __shared__ float smem[128*20 + 128*20];
    const int z = blockIdx.z, b = z >> 3, h = z & 7;
    const float* Aq = qkv + ((size_t)(b*KKK) + blockIdx.y*128)*(3*DDD) + h*HDIM;
    const float* Bk = qkv + ((size_t)(b*KKK) + blockIdx.x*128)*(3*DDD) + DDD + h*HDIM;
    float acc[2][8][4] = {};
    mma_core<128,true>(Aq, 3*DDD, Bk, 3*DDD, HDIM, smem, acc);

    float* Cb = logits + ((size_t)z*KKK + blockIdx.y*128)*KKK + blockIdx.x*128;
    const int tid  = threadIdx.x;
    const int warp = tid >> 5, lane = tid & 31;
    const int wr = warp & 3, wc = warp >> 2;
    const int g = lane >> 2, t = lane & 3;
    const int r0 = wr*32, c0 = wc*64;

    #pragma unroll
    for (int mf = 0; mf < 2; mf++){
        #pragma unroll
        for (int nf = 0; nf < 8; nf++){
            const int col = c0 + nf*8 + t*2;
            #pragma unroll
            for (int half = 0; half < 2; half++){
                const int r = r0 + mf*16 + g + half*8;
                float2* p = (float2*)(Cb + (size_t)r*KKK + col);
                float2 o = *p;
                o.x += 0.125f*acc[mf][nf][half*2];
                o.y += 0.125f*acc[mf][nf][half*2+1];
                *p = o;
            }
        }
    }
}

// ---------- AV via tensor cores: out[b,q,h*64+d] = P @ V ----------
__global__ void __launch_bounds__(256) mma_av(
    const float* __restrict__ logits, const float* __restrict__ qkv,
    float* __restrict__ out)
{
    __shared__ float smem[128*20 + 16*72];
    const int z = blockIdx.z, b = z >> 3, h = z & 7;
    const float* Ap = logits + ((size_t)z*KKK + blockIdx.y*128)*KKK;
    const float* Bv = qkv + (size_t)(b*KKK)*(3*DDD) + 2*DDD + h*HDIM;
    float acc[2][4][4] = {};
    mma_core<64,false>(Ap, KKK, Bv, 3*DDD, KKK, smem, acc);

    float* Cb = out + ((size_t)(b*KKK) + blockIdx.y*128)*DDD + h*HDIM;
    const int tid  = threadIdx.x;
    const int warp = tid >> 5, lane = tid & 31;
    const int wr = warp & 3, wc = warp >> 2;
    const int g = lane >> 2, t = lane & 3;
    const int r0 = wr*32, c0 = wc*32;

    #pragma unroll
    for (int mf = 0; mf < 2; mf++){
        #pragma unroll
        for (int nf = 0; nf < 4; nf++){
            const int col = c0 + nf*8 + t*2;
            #pragma unroll
            for (int half = 0; half < 2; half++){
                const int r = r0 + mf*16 + g + half*8;
                *(float2*)(Cb + (size_t)r*DDD + col) =
                    make_float2(acc[mf][nf][half*2], acc[mf][nf][half*2+1]);
            }
        }
    }
}

// ---------- LayerNorm: one block per row (512 elems) ----------
__global__ void __launch_bounds__(128) ln_kernel(
    const float* __restrict__ in, const float* __restrict__ w,
    const float* __restrict__ b, float* __restrict__ out)
{
    const int row = blockIdx.x;
    const int t = threadIdx.x;  // 128
    float4 v = ((const float4*)(in + (size_t)row*DDD))[t];
    float s  = v.x+v.y+v.z+v.w;
    float ss = v.x*v.x+v.y*v.y+v.z*v.z+v.w*v.w;
    #pragma unroll
    for (int o=16;o>0;o>>=1){
        s  += __shfl_xor_sync(0xffffffffu, s,  o);
        ss += __shfl_xor_sync(0xffffffffu, ss, o);
    }
    __shared__ float sm[8];
    const int wid = t>>5, lid = t&31;
    if (lid==0){ sm[wid]=s; sm[4+wid]=ss; }
    __syncthreads();
    s  = sm[0]+sm[1]+sm[2]+sm[3];
    ss = sm[4]+sm[5]+sm[6]+sm[7];
    const float mean = s*(1.0f/DDD);
    const float var  = ss*(1.0f/DDD) - mean*mean;
    const float inv  = rsqrtf(var + 1e-5f);
    float4 wv = ((const float4*)w)[t];
    float4 bv = ((const float4*)b)[t];
    float4 o4;
    o4.x = (v.x-mean)*inv*wv.x + bv.x;
    o4.y = (v.y-mean)*inv*wv.y + bv.y;
    o4.z = (v.z-mean)*inv*wv.z + bv.z;
    o4.w = (v.w-mean)*inv*wv.w + bv.w;
    ((float4*)(out + (size_t)row*DDD))[t] = o4;
}

// ---------- Edge bias (HBM-bound): logits = edge_b + pairwise @ edge_w ----------
__global__ void __launch_bounds__(128) edge_bias_kernel(
    const float* __restrict__ pw, const float* __restrict__ ew,
    const float* __restrict__ eb, float* __restrict__ logits)
{
    __shared__ float ews[DPP*NH];  // [d][h]
    const int q = blockIdx.x;
    const int b = blockIdx.y;
    const int tid = threadIdx.x;   // 128
    ((float4*)ews)[tid]       = ((const float4*)ew)[tid];
    ((float4*)ews)[tid + 128] = ((const float4*)ew)[tid + 128];
    __syncthreads();

    const int k0 = tid*4;
    const float* base = pw + (((size_t)b*KKK + q)*KKK + k0)*DPP;

    u64 acc[4][4];   // [k-sub][head-pair]
    #pragma unroll
    for (int j=0;j<4;j++){
        u64 ini = pack2f(eb[2*j], eb[2*j+1]);
        #pragma unroll
        for (int g=0;g<4;g++) acc[g][j] = ini;
    }

    #pragma unroll 4
    for (int d4=0; d4<32; d4++){
        float4 p[4];
        #pragma unroll
        for (int g=0;g<4;g++)
            p[g] = *(const float4*)(base + (size_t)g*DPP + d4*4);
        #pragma unroll
        for (int x=0;x<4;x++){
            const int d = d4*4 + x;
            const u64* e2 = (const u64*)&ews[d*NH];
            u64 e0=e2[0], e1=e2[1], e2v=e2[2], e3=e2[3];
            #pragma unroll
            for (int g=0;g<4;g++){
                const float pv = (x==0)?p[g].x : (x==1)?p[g].y : (x==2)?p[g].z : p[g].w;
                u64 pd = dup2f(pv);
                ffma2(acc[g][0], pd, e0);
                ffma2(acc[g][1], pd, e1);
                ffma2(acc[g][2], pd, e2v);
                ffma2(acc[g][3], pd, e3);
            }
        }
    }

    #pragma unroll
    for (int j=0;j<4;j++){
        float x0,y0,x1,y1,x2,y2,x3,y3;
        unpack2f(acc[0][j],x0,y0); unpack2f(acc[1][j],x1,y1);
        unpack2f(acc[2][j],x2,y2); unpack2f(acc[3][j],x3,y3);
        const size_t b0 = (((size_t)(b*NH + 2*j  )*KKK + q)*KKK) + k0;
        const size_t b1 = (((size_t)(b*NH + 2*j+1)*KKK + q)*KKK) + k0;
        *(float4*)(logits + b0) = make_float4(x0,x1,x2,x3);
        *(float4*)(logits + b1) = make_float4(y0,y1,y2,y3);
    }
}

// ---------- Softmax over last dim (512) ----------
__global__ void __launch_bounds__(128) softmax_kernel(float* __restrict__ logits)
{
    const size_t row = blockIdx.x;
    float* p = logits + row*KKK;
    const int t = threadIdx.x;
    float4 v = ((float4*)p)[t];
    float m = fmaxf(fmaxf(v.x,v.y), fmaxf(v.z,v.w));
    #pragma unroll
    for (int o=16;o>0;o>>=1) m = fmaxf(m, __shfl_xor_sync(0xffffffffu,m,o));
    __shared__ float smx[4], sms[4];
    const int wid=t>>5, lid=t&31;
    if (lid==0) smx[wid]=m;
    __syncthreads();
    m = fmaxf(fmaxf(smx[0],smx[1]), fmaxf(smx[2],smx[3]));
    v.x = expf(v.x-m); v.y = expf(v.y-m); v.z = expf(v.z-m); v.w = expf(v.w-m);
    float s = v.x+v.y+v.z+v.w;
    #pragma unroll
    for (int o=16;o>0;o>>=1) s += __shfl_xor_sync(0xffffffffu,s,o);
    if (lid==0) sms[wid]=s;
    __syncthreads();
    s = sms[0]+sms[1]+sms[2]+sms[3];
    const float r = 1.0f/s;
    v.x*=r; v.y*=r; v.z*=r; v.w*=r;
    ((float4*)p)[t] = v;
}

// ---------- host launch ----------
extern "C" void kernel_launch(void* const* d_in, const int* in_sizes, int n_in,
                              void* d_out, int out_size)
{
    const float* slots    = (const float*)d_in[0];
    const float* pairwise = (const float*)d_in[1];
    const float* ln1w     = (const float*)d_in[2];
    const float* ln1b     = (const float*)d_in[3];
    const float* ln2w     = (const float*)d_in[4];
    const float* ln2b     = (const float*)d_in[5];
    const float* wqkv     = (const float*)d_in[6];
    const float* edge_w   = (const float*)d_in[7];
    const float* edge_b   = (const float*)d_in[8];
    const float* out_w    = (const float*)d_in[9];
    const float* out_b    = (const float*)d_in[10];
    const float* ffn_w1   = (const float*)d_in[11];
    const float* ffn_b1   = (const float*)d_in[12];
    const float* ffn_w2   = (const float*)d_in[13];
    const float* ffn_b2   = (const float*)d_in[14];
    float* out = (float*)d_out;

    float *x_, *qkv_, *log_, *ao_, *s2_, *ffn_;
    cudaGetSymbolAddress((void**)&x_,   g_x);
    cudaGetSymbolAddress((void**)&qkv_, g_qkv);
    cudaGetSymbolAddress((void**)&log_, g_logits);
    cudaGetSymbolAddress((void**)&ao_,  g_attnout);
    cudaGetSymbolAddress((void**)&s2_,  g_slots2);
    cudaGetSymbolAddress((void**)&ffn_, g_ffn);

    // 1) LN1
    ln_kernel<<<MROWS,128>>>(slots, ln1w, ln1b, x_);
    // 2) QKV projection (2048 x 1536 x 512), tf32 tensor cores
    mma_proj<128,0><<<dim3(3*DDD/128, MROWS/128), 256>>>(
        x_, wqkv, nullptr, nullptr, qkv_, DDD, 3*DDD, DDD);
    // 3) edge bias -> logits
    edge_bias_kernel<<<dim3(KKK,BB),128>>>(pairwise, edge_w, edge_b, log_);
    // 4) logits += 0.125 * QK^T  (tensor cores)
    mma_qk<<<dim3(KKK/128, KKK/128, BH), 256>>>(qkv_, log_);
    // 5) softmax
    softmax_kernel<<<BH*KKK,128>>>(log_);
    // 6) attn @ V -> (B,K,D)  (tensor cores)
    mma_av<<<dim3(1, KKK/128, BH), 256>>>(log_, qkv_, ao_);
    // 7) out projection + residual (2048 x 512 x 512)
    mma_proj<64,2><<<dim3(DDD/64, MROWS/128), 256>>>(
        ao_, out_w, out_b, slots, s2_, DDD, DDD, DDD);
    // 8) LN2
    ln_kernel<<<MROWS,128>>>(s2_, ln2w, ln2b, x_);
    // 9) FFN1 + exact GELU (2048 x 2048 x 512)
    mma_proj<128,1><<<dim3(4*DDD/128, MROWS/128), 256>>>(
        x_, ffn_w1, ffn_b1, nullptr, ffn_, DDD, 4*DDD, DDD);
    // 10) FFN2 + residual (2048 x 512 x 2048) -> final output
    mma_proj<64,2><<<dim3(DDD/64, MROWS/128), 256>>>(
        ffn_, ffn_w2, ffn_b2, s2_, out, 4*DDD, DDD, 4*DDD);
}

// round 15
// speedup vs baseline: 1.0097x; 1.0012x over previous
#include <cuda_runtime.h>
#include <math.h>

// Problem constants
#define BB 4
#define KKK 512          // slots per batch
#define DDD 512          // slot dim
#define DPP 128          // pairwise dim
#define NH 8             // heads
#define HDIM 64          // head dim
#define MROWS (BB*KKK)   // 2048
#define BH (BB*NH)       // 32

typedef unsigned u32;
typedef unsigned long long u64;

// ---------- packed fp32x2 helpers (edge bias kernel) ----------
__device__ __forceinline__ u64 dup2f(float x){
    u64 r; unsigned xi = __float_as_uint(x);
    asm("mov.b64 %0, {%1,%1};" : "=l"(r) : "r"(xi));
    return r;
}
__device__ __forceinline__ u64 pack2f(float x, float y){
    u64 r;
    asm("mov.b64 %0, {%1,%2};" : "=l"(r) : "r"(__float_as_uint(x)), "r"(__float_as_uint(y)));
    return r;
}
__device__ __forceinline__ void unpack2f(u64 v, float &x, float &y){
    unsigned a,b;
    asm("mov.b64 {%0,%1}, %2;" : "=r"(a), "=r"(b) : "l"(v));
    x = __uint_as_float(a); y = __uint_as_float(b);
}
__device__ __forceinline__ void ffma2(u64 &d, u64 a, u64 b){
    asm("fma.rn.f32x2 %0, %1, %2, %0;" : "+l"(d) : "l"(a), "l"(b));
}

// ---------- tf32 MMA helpers ----------
__device__ __forceinline__ float to_tf32(float x){
    float r; asm("cvt.rna.tf32.f32 %0, %1;" : "=f"(r) : "f"(x)); return r;
}
__device__ __forceinline__ float4 cvt4(float4 v){
    v.x = to_tf32(v.x); v.y = to_tf32(v.y);
    v.z = to_tf32(v.z); v.w = to_tf32(v.w);
    return v;
}
__device__ __forceinline__ void mma8(float* c, const u32* a, const u32* b){
    asm("mma.sync.aligned.m16n8k8.row.col.f32.tf32.tf32.f32 "
        "{%0,%1,%2,%3}, {%4,%5,%6,%7}, {%8,%9}, {%0,%1,%2,%3};"
        : "+f"(c[0]), "+f"(c[1]), "+f"(c[2]), "+f"(c[3])
        : "r"(a[0]), "r"(a[1]), "r"(a[2]), "r"(a[3]),
          "r"(b[0]), "r"(b[1]));
}

// ---------- scratch (no dynamic allocation allowed) ----------
__device__ float g_x[MROWS*DDD];
__device__ float g_qkv[MROWS*3*DDD];
__device__ float g_logits[(size_t)BH*KKK*KKK];   // 33.5 MB
__device__ float g_attnout[MROWS*DDD];
__device__ float g_slots2[MROWS*DDD];
__device__ float g_ffn[MROWS*4*DDD];

// =====================================================================
// mma_core: C(128 x BN) += A(128 x Ktot) * B(Ktot x BN), tf32 tensor path
//   A row-major (lda), staged to As[m][20]        (stride 20, conflict-free)
//   B:
//     BNK=false: global row-major K x N (weights)  -> Bs[k][BN+8]
//     BNK=true : global row-major N x K (K-slots)  -> Bs[n][20] (no transpose)
//   256 threads = 8 warps (4 m-rows x 2 n-cols), warp tile 32 x (BN/2).
//   Register-prefetch pipeline over single smem buffer.
// =====================================================================
template<int BN, bool BNK>
__device__ __forceinline__ void mma_core(
    const float* __restrict__ A, int lda,
    const float* __restrict__ B, int ldb,
    int Ktot, float* smem, float (&acc)[2][BN/16][4])
{
    constexpr int NF = BN/16;
    constexpr int SB = BN + 8;       // 136 or 72; both ≡ 8 (mod 32)
    constexpr int BITER = BN/64;     // B-loader iterations (2 or 1)
    float* As = smem;                // 128*20 floats
    float* Bs = smem + 128*20;

    const int tid  = threadIdx.x;
    const int warp = tid >> 5, lane = tid & 31;
    const int wr = warp & 3, wc = warp >> 2;
    const int g = lane >> 2, t = lane & 3;
    const int mw = wr * 32, nw = wc * (BN/2);

    // A loader mapping: 128x16 tile, 512 float4, 2 per thread
    const int ar0 = tid >> 2,  ac0 = (tid & 3) * 4;
    const int ar1 = (tid+256) >> 2, ac1 = ((tid+256) & 3) * 4;

    float4 pa0, pa1, pb0, pb1;

    // prologue: fetch tile 0
    pa0 = cvt4(*(const float4*)(A + (size_t)ar0*lda + ac0));
    pa1 = cvt4(*(const float4*)(A + (size_t)ar1*lda + ac1));
    if (BNK){
        pb0 = cvt4(*(const float4*)(B + (size_t)ar0*ldb + ac0));
        if (BITER == 2)
            pb1 = cvt4(*(const float4*)(B + (size_t)ar1*ldb + ac1));
    } else {
        const int br = tid / (BN/4), bc = (tid % (BN/4)) * 4;
        pb0 = cvt4(*(const float4*)(B + (size_t)br*ldb + bc));
        if (BITER == 2){
            const int br2 = (tid+256) / (BN/4), bc2 = ((tid+256) % (BN/4)) * 4;
            pb1 = cvt4(*(const float4*)(B + (size_t)br2*ldb + bc2));
        }
    }
    // store tile 0
    *(float4*)(As + ar0*20 + ac0) = pa0;
    *(float4*)(As + ar1*20 + ac1) = pa1;
    if (BNK){
        *(float4*)(Bs + ar0*20 + ac0) = pb0;
        if (BITER == 2) *(float4*)(Bs + ar1*20 + ac1) = pb1;
    } else {
        const int br = tid / (BN/4), bc = (tid % (BN/4)) * 4;
        *(float4*)(Bs + br*SB + bc) = pb0;
        if (BITER == 2){
            const int br2 = (tid+256) / (BN/4), bc2 = ((tid+256) % (BN/4)) * 4;
            *(float4*)(Bs + br2*SB + bc2) = pb1;
        }
    }
    __syncthreads();

    for (int k0 = 0; k0 < Ktot; k0 += 16){
        const bool notlast = (k0 + 16 < Ktot);
        // prefetch next tile into registers
        if (notlast){
            const int kn = k0 + 16;
            pa0 = cvt4(*(const float4*)(A + (size_t)ar0*lda + kn + ac0));
            pa1 = cvt4(*(const float4*)(A + (size_t)ar1*lda + kn + ac1));
            if (BNK){
                pb0 = cvt4(*(const float4*)(B + (size_t)ar0*ldb + kn + ac0));
                if (BITER == 2)
                    pb1 = cvt4(*(const float4*)(B + (size_t)ar1*ldb + kn + ac1));
            } else {
                const int br = tid / (BN/4), bc = (tid % (BN/4)) * 4;
                pb0 = cvt4(*(const float4*)(B + (size_t)(kn+br)*ldb + bc));
                if (BITER == 2){
                    const int br2 = (tid+256) / (BN/4), bc2 = ((tid+256) % (BN/4)) * 4;
                    pb1 = cvt4(*(const float4*)(B + (size_t)(kn+br2)*ldb + bc2));
                }
            }
        }
        // compute on current smem tile
        #pragma unroll
        for (int ks = 0; ks < 2; ks++){
            const int kk = ks * 8;
            u32 af[2][4];
            #pragma unroll
            for (int mf = 0; mf < 2; mf++){
                const int mb = mw + mf*16;
                af[mf][0] = __float_as_uint(As[(mb+g)*20   + kk + t]);
                af[mf][1] = __float_as_uint(As[(mb+8+g)*20 + kk + t]);
                af[mf][2] = __float_as_uint(As[(mb+g)*20   + kk + 4 + t]);
                af[mf][3] = __float_as_uint(As[(mb+8+g)*20 + kk + 4 + t]);
            }
            u32 bf[NF][2];
            #pragma unroll
            for (int nf = 0; nf < NF; nf++){
                const int nb = nw + nf*8;
                if (BNK){
                    bf[nf][0] = __float_as_uint(Bs[(nb+g)*20 + kk + t]);
                    bf[nf][1] = __float_as_uint(Bs[(nb+g)*20 + kk + 4 + t]);
                } else {
                    bf[nf][0] = __float_as_uint(Bs[(kk+t)*SB   + nb + g]);
                    bf[nf][1] = __float_as_uint(Bs[(kk+4+t)*SB + nb + g]);
                }
            }
            #pragma unroll
            for (int mf = 0; mf < 2; mf++)
                #pragma unroll
                for (int nf = 0; nf < NF; nf++)
                    mma8(acc[mf][nf], af[mf], bf[nf]);
        }
        __syncthreads();
        if (notlast){
            *(float4*)(As + ar0*20 + ac0) = pa0;
            *(float4*)(As + ar1*20 + ac1) = pa1;
            if (BNK){
                *(float4*)(Bs + ar0*20 + ac0) = pb0;
                if (BITER == 2) *(float4*)(Bs + ar1*20 + ac1) = pb1;
            } else {
                const int br = tid / (BN/4), bc = (tid % (BN/4)) * 4;
                *(float4*)(Bs + br*SB + bc) = pb0;
                if (BITER == 2){
                    const int br2 = (tid+256) / (BN/4), bc2 = ((tid+256) % (BN/4)) * 4;
                    *(float4*)(Bs + br2*SB + bc2) = pb1;
                }
            }
            __syncthreads();
        }
    }
}

// ---------- projection GEMM + fused epilogues ----------
// EPI: 0 = none, 1 = +bias then exact GELU, 2 = +bias then +residual
template<int BN, int EPI>
__global__ void __launch_bounds__(256) mma_proj(
    const float* __restrict__ A, const float* __restrict__ Bw,
    const float* __restrict__ bias, const float* __restrict__ Res,
    float* __restrict__ C, int lda, int N, int Ktot)
{
    __shared__ float smem[128*20 + 16*(BN+8)];
    const float* Ab = A  + (size_t)blockIdx.y*128*lda;
    const float* Bb = Bw + blockIdx.x*BN;
    float acc[2][BN/16][4] = {};
    mma_core<BN,false>(Ab, lda, Bb, N, Ktot, smem, acc);

    const int tid  = threadIdx.x;
    const int warp = tid >> 5, lane = tid & 31;
    const int wr = warp & 3, wc = warp >> 2;
    const int g = lane >> 2, t = lane & 3;
    const size_t row0 = (size_t)blockIdx.y*128 + wr*32;
    const int col0 = blockIdx.x*BN + wc*(BN/2);

    #pragma unroll
    for (int mf = 0; mf < 2; mf++){
        #pragma unroll
        for (int nf = 0; nf < BN/16; nf++){
            const int col = col0 + nf*8 + t*2;
            float b0 = 0.f, b1 = 0.f;
            if (EPI != 0){ b0 = bias[col]; b1 = bias[col+1]; }
            #pragma unroll
            for (int half = 0; half < 2; half++){
                const size_t r = row0 + mf*16 + g + half*8;
                float v0 = acc[mf][nf][half*2]   + b0;
                float v1 = acc[mf][nf][half*2+1] + b1;
                if (EPI == 1){
                    v0 = 0.5f*v0*(1.0f + erff(v0*0.70710678118654752f));
                    v1 = 0.5f*v1*(1.0f + erff(v1*0.70710678118654752f));
                }
                if (EPI == 2){
                    float2 rr = *(const float2*)(Res + r*(size_t)N + col);
                    v0 += rr.x; v1 += rr.y;
                }
                *(float2*)(C + r*(size_t)N + col) = make_float2(v0, v1);
            }
        }
    }
}

// ---------- QK^T via tensor cores: logits += 0.125 * Q K^T ----------
__global__ void __launch_bounds__(256) mma_qk(
    const float* __restrict__ qkv, float* __restrict__ logits)
{
    __shared__ float smem[128*20 + 128*20];
    const int z = blockIdx.z, b = z >> 3, h = z & 7;
    const float* Aq = qkv + ((size_t)(b*KKK) + blockIdx.y*128)*(3*DDD) + h*HDIM;
    const float* Bk = qkv + ((size_t)(b*KKK) + blockIdx.x*128)*(3*DDD) + DDD + h*HDIM;
    float acc[2][8][4] = {};
    mma_core<128,true>(Aq, 3*DDD, Bk, 3*DDD, HDIM, smem, acc);

    float* Cb = logits + ((size_t)z*KKK + blockIdx.y*128)*KKK + blockIdx.x*128;
    const int tid  = threadIdx.x;
    const int warp = tid >> 5, lane = tid & 31;
    const int wr = warp & 3, wc = warp >> 2;
    const int g = lane >> 2, t = lane & 3;
    const int r0 = wr*32, c0 = wc*64;

    #pragma unroll
    for (int mf = 0; mf < 2; mf++){
        #pragma unroll
        for (int nf = 0; nf < 8; nf++){
            const int col = c0 + nf*8 + t*2;
            #pragma unroll
            for (int half = 0; half < 2; half++){
                const int r = r0 + mf*16 + g + half*8;
                float2* p = (float2*)(Cb + (size_t)r*KKK + col);
                float2 o = *p;
                o.x += 0.125f*acc[mf][nf][half*2];
                o.y += 0.125f*acc[mf][nf][half*2+1];
                *p = o;
            }
        }
    }
}

// ---------- AV via tensor cores: out[b,q,h*64+d] = P @ V ----------
__global__ void __launch_bounds__(256) mma_av(
    const float* __restrict__ logits, const float* __restrict__ qkv,
    float* __restrict__ out)
{
    __shared__ float smem[128*20 + 16*72];
    const int z = blockIdx.z, b = z >> 3, h = z & 7;
    const float* Ap = logits + ((size_t)z*KKK + blockIdx.y*128)*KKK;
    const float* Bv = qkv + (size_t)(b*KKK)*(3*DDD) + 2*DDD + h*HDIM;
    float acc[2][4][4] = {};
    mma_core<64,false>(Ap, KKK, Bv, 3*DDD, KKK, smem, acc);

    float* Cb = out + ((size_t)(b*KKK) + blockIdx.y*128)*DDD + h*HDIM;
    const int tid  = threadIdx.x;
    const int warp = tid >> 5, lane = tid & 31;
    const int wr = warp & 3, wc = warp >> 2;
    const int g = lane >> 2, t = lane & 3;
    const int r0 = wr*32, c0 = wc*32;

    #pragma unroll
    for (int mf = 0; mf < 2; mf++){
        #pragma unroll
        for (int nf = 0; nf < 4; nf++){
            const int col = c0 + nf*8 + t*2;
            #pragma unroll
            for (int half = 0; half < 2; half++){
                const int r = r0 + mf*16 + g + half*8;
                *(float2*)(Cb + (size_t)r*DDD + col) =
                    make_float2(acc[mf][nf][half*2], acc[mf][nf][half*2+1]);
            }
        }
    }
}

// ---------- LayerNorm: one block per row (512 elems) ----------
__global__ void __launch_bounds__(128) ln_kernel(
    const float* __restrict__ in, const float* __restrict__ w,
    const float* __restrict__ b, float* __restrict__ out)
{
    const int row = blockIdx.x;
    const int t = threadIdx.x;  // 128
    float4 v = ((const float4*)(in + (size_t)row*DDD))[t];
    float s  = v.x+v.y+v.z+v.w;
    float ss = v.x*v.x+v.y*v.y+v.z*v.z+v.w*v.w;
    #pragma unroll
    for (int o=16;o>0;o>>=1){
        s  += __shfl_xor_sync(0xffffffffu, s,  o);
        ss += __shfl_xor_sync(0xffffffffu, ss, o);
    }
    __shared__ float sm[8];
    const int wid = t>>5, lid = t&31;
    if (lid==0){ sm[wid]=s; sm[4+wid]=ss; }
    __syncthreads();
    s  = sm[0]+sm[1]+sm[2]+sm[3];
    ss = sm[4]+sm[5]+sm[6]+sm[7];
    const float mean = s*(1.0f/DDD);
    const float var  = ss*(1.0f/DDD) - mean*mean;
    const float inv  = rsqrtf(var + 1e-5f);
    float4 wv = ((const float4*)w)[t];
    float4 bv = ((const float4*)b)[t];
    float4 o4;
    o4.x = (v.x-mean)*inv*wv.x + bv.x;
    o4.y = (v.y-mean)*inv*wv.y + bv.y;
    o4.z = (v.z-mean)*inv*wv.z + bv.z;
    o4.w = (v.w-mean)*inv*wv.w + bv.w;
    ((float4*)(out + (size_t)row*DDD))[t] = o4;
}

// ---------- Edge bias (HBM-bound): logits = edge_b + pairwise @ edge_w ----------
__global__ void __launch_bounds__(128) edge_bias_kernel(
    const float* __restrict__ pw, const float* __restrict__ ew,
    const float* __restrict__ eb, float* __restrict__ logits)
{
    __shared__ float ews[DPP*NH];  // [d][h]
    const int q = blockIdx.x;
    const int b = blockIdx.y;
    const int tid = threadIdx.x;   // 128
    ((float4*)ews)[tid]       = ((const float4*)ew)[tid];
    ((float4*)ews)[tid + 128] = ((const float4*)ew)[tid + 128];
    __syncthreads();

    const int k0 = tid*4;
    const float* base = pw + (((size_t)b*KKK + q)*KKK + k0)*DPP;

    u64 acc[4][4];   // [k-sub][head-pair]
    #pragma unroll
    for (int j=0;j<4;j++){
        u64 ini = pack2f(eb[2*j], eb[2*j+1]);
        #pragma unroll
        for (int g=0;g<4;g++) acc[g][j] = ini;
    }

    #pragma unroll 4
    for (int d4=0; d4<32; d4++){
        float4 p[4];
        #pragma unroll
        for (int g=0;g<4;g++)
            p[g] = *(const float4*)(base + (size_t)g*DPP + d4*4);
        #pragma unroll
        for (int x=0;x<4;x++){
            const int d = d4*4 + x;
            const u64* e2 = (const u64*)&ews[d*NH];
            u64 e0=e2[0], e1=e2[1], e2v=e2[2], e3=e2[3];
            #pragma unroll
            for (int g=0;g<4;g++){
                const float pv = (x==0)?p[g].x : (x==1)?p[g].y : (x==2)?p[g].z : p[g].w;
                u64 pd = dup2f(pv);
                ffma2(acc[g][0], pd, e0);
                ffma2(acc[g][1], pd, e1);
                ffma2(acc[g][2], pd, e2v);
                ffma2(acc[g][3], pd, e3);
            }
        }
    }

    #pragma unroll
    for (int j=0;j<4;j++){
        float x0,y0,x1,y1,x2,y2,x3,y3;
        unpack2f(acc[0][j],x0,y0); unpack2f(acc[1][j],x1,y1);
        unpack2f(acc[2][j],x2,y2); unpack2f(acc[3][j],x3,y3);
        const size_t b0 = (((size_t)(b*NH + 2*j  )*KKK + q)*KKK) + k0;
        const size_t b1 = (((size_t)(b*NH + 2*j+1)*KKK + q)*KKK) + k0;
        *(float4*)(logits + b0) = make_float4(x0,x1,x2,x3);
        *(float4*)(logits + b1) = make_float4(y0,y1,y2,y3);
    }
}

// ---------- Softmax over last dim (512) ----------
__global__ void __launch_bounds__(128) softmax_kernel(float* __restrict__ logits)
{
    const size_t row = blockIdx.x;
    float* p = logits + row*KKK;
    const int t = threadIdx.x;
    float4 v = ((float4*)p)[t];
    float m = fmaxf(fmaxf(v.x,v.y), fmaxf(v.z,v.w));
    #pragma unroll
    for (int o=16;o>0;o>>=1) m = fmaxf(m, __shfl_xor_sync(0xffffffffu,m,o));
    __shared__ float smx[4], sms[4];
    const int wid=t>>5, lid=t&31;
    if (lid==0) smx[wid]=m;
    __syncthreads();
    m = fmaxf(fmaxf(smx[0],smx[1]), fmaxf(smx[2],smx[3]));
    v.x = expf(v.x-m); v.y = expf(v.y-m); v.z = expf(v.z-m); v.w = expf(v.w-m);
    float s = v.x+v.y+v.z+v.w;
    #pragma unroll
    for (int o=16;o>0;o>>=1) s += __shfl_xor_sync(0xffffffffu,s,o);
    if (lid==0) sms[wid]=s;
    __syncthreads();
    s = sms[0]+sms[1]+sms[2]+sms[3];
    const float r = 1.0f/s;
    v.x*=r; v.y*=r; v.z*=r; v.w*=r;
    ((float4*)p)[t] = v;
}

// ---------- host launch ----------
extern "C" void kernel_launch(void* const* d_in, const int* in_sizes, int n_in,
                              void* d_out, int out_size)
{
    const float* slots    = (const float*)d_in[0];
    const float* pairwise = (const float*)d_in[1];
    const float* ln1w     = (const float*)d_in[2];
    const float* ln1b     = (const float*)d_in[3];
    const float* ln2w     = (const float*)d_in[4];
    const float* ln2b     = (const float*)d_in[5];
    const float* wqkv     = (const float*)d_in[6];
    const float* edge_w   = (const float*)d_in[7];
    const float* edge_b   = (const float*)d_in[8];
    const float* out_w    = (const float*)d_in[9];
    const float* out_b    = (const float*)d_in[10];
    const float* ffn_w1   = (const float*)d_in[11];
    const float* ffn_b1   = (const float*)d_in[12];
    const float* ffn_w2   = (const float*)d_in[13];
    const float* ffn_b2   = (const float*)d_in[14];
    float* out = (float*)d_out;

    float *x_, *qkv_, *log_, *ao_, *s2_, *ffn_;
    cudaGetSymbolAddress((void**)&x_,   g_x);
    cudaGetSymbolAddress((void**)&qkv_, g_qkv);
    cudaGetSymbolAddress((void**)&log_, g_logits);
    cudaGetSymbolAddress((void**)&ao_,  g_attnout);
    cudaGetSymbolAddress((void**)&s2_,  g_slots2);
    cudaGetSymbolAddress((void**)&ffn_, g_ffn);

    // 1) LN1
    ln_kernel<<<MROWS,128>>>(slots, ln1w, ln1b, x_);
    // 2) QKV projection (2048 x 1536 x 512), tf32 tensor cores
    mma_proj<128,0><<<dim3(3*DDD/128, MROWS/128), 256>>>(
        x_, wqkv, nullptr, nullptr, qkv_, DDD, 3*DDD, DDD);
    // 3) edge bias -> logits
    edge_bias_kernel<<<dim3(KKK,BB),128>>>(pairwise, edge_w, edge_b, log_);
    // 4) logits += 0.125 * QK^T  (tensor cores)
    mma_qk<<<dim3(KKK/128, KKK/128, BH), 256>>>(qkv_, log_);
    // 5) softmax
    softmax_kernel<<<BH*KKK,128>>>(log_);
    // 6) attn @ V -> (B,K,D)  (tensor cores)
    mma_av<<<dim3(1, KKK/128, BH), 256>>>(log_, qkv_, ao_);
    // 7) out projection + residual (2048 x 512 x 512)
    mma_proj<64,2><<<dim3(DDD/64, MROWS/128), 256>>>(
        ao_, out_w, out_b, slots, s2_, DDD, DDD, DDD);
    // 8) LN2
    ln_kernel<<<MROWS,128>>>(s2_, ln2w, ln2b, x_);
    // 9) FFN1 + exact GELU (2048 x 2048 x 512)
    mma_proj<128,1><<<dim3(4*DDD/128, MROWS/128), 256>>>(
        x_, ffn_w1, ffn_b1, nullptr, ffn_, DDD, 4*DDD, DDD);
    // 10) FFN2 + residual (2048 x 512 x 2048) -> final output
    mma_proj<64,2><<<dim3(DDD/64, MROWS/128), 256>>>(
        ffn_, ffn_w2, ffn_b2, s2_, out, 4*DDD, DDD, 4*DDD);
}

// round 16
// speedup vs baseline: 1.0771x; 1.0667x over previous
#include <cuda_runtime.h>
#include <math.h>

// Problem constants
#define BB 4
#define KKK 512          // slots per batch
#define DDD 512          // slot dim
#define DPP 128          // pairwise dim
#define NH 8             // heads
#define HDIM 64          // head dim
#define MROWS (BB*KKK)   // 2048
#define BH (BB*NH)       // 32

typedef unsigned u32;
typedef unsigned long long u64;

// ---------- packed fp32x2 helpers (edge bias kernel) ----------
__device__ __forceinline__ u64 dup2f(float x){
    u64 r; unsigned xi = __float_as_uint(x);
    asm("mov.b64 %0, {%1,%1};" : "=l"(r) : "r"(xi));
    return r;
}
__device__ __forceinline__ u64 pack2f(float x, float y){
    u64 r;
    asm("mov.b64 %0, {%1,%2};" : "=l"(r) : "r"(__float_as_uint(x)), "r"(__float_as_uint(y)));
    return r;
}
__device__ __forceinline__ void unpack2f(u64 v, float &x, float &y){
    unsigned a,b;
    asm("mov.b64 {%0,%1}, %2;" : "=r"(a), "=r"(b) : "l"(v));
    x = __uint_as_float(a); y = __uint_as_float(b);
}
__device__ __forceinline__ void ffma2(u64 &d, u64 a, u64 b){
    asm("fma.rn.f32x2 %0, %1, %2, %0;" : "+l"(d) : "l"(a), "l"(b));
}

// ---------- tf32 MMA helpers ----------
__device__ __forceinline__ float to_tf32(float x){
    float r; asm("cvt.rna.tf32.f32 %0, %1;" : "=f"(r) : "f"(x)); return r;
}
__device__ __forceinline__ float4 cvt4(float4 v){
    v.x = to_tf32(v.x); v.y = to_tf32(v.y);
    v.z = to_tf32(v.z); v.w = to_tf32(v.w);
    return v;
}
__device__ __forceinline__ void mma8(float* c, const u32* a, const u32* b){
    asm("mma.sync.aligned.m16n8k8.row.col.f32.tf32.tf32.f32 "
        "{%0,%1,%2,%3}, {%4,%5,%6,%7}, {%8,%9}, {%0,%1,%2,%3};"
        : "+f"(c[0]), "+f"(c[1]), "+f"(c[2]), "+f"(c[3])
        : "r"(a[0]), "r"(a[1]), "r"(a[2]), "r"(a[3]),
          "r"(b[0]), "r"(b[1]));
}

// ---------- scratch (no dynamic allocation allowed) ----------
__device__ float g_x[MROWS*DDD];
__device__ float g_qkv[MROWS*3*DDD];
__device__ float g_logits[(size_t)BH*KKK*KKK];   // edge bias buffer (33.5 MB)
__device__ float g_attnout[MROWS*DDD];
__device__ float g_slots2[MROWS*DDD];
__device__ float g_ffn[MROWS*4*DDD];

// =====================================================================
// mma_proj: C(128 x BN per block) = A(M x Ktot) @ B(Ktot x N), tf32 MMA,
// double-buffered smem (ONE __syncthreads per k16 tile).
// EPI: 0 = none, 1 = +bias then exact GELU, 2 = +bias then +residual
// =====================================================================
template<int BN, int EPI>
__global__ void __launch_bounds__(256) mma_proj(
    const float* __restrict__ A, const float* __restrict__ Bw,
    const float* __restrict__ bias, const float* __restrict__ Res,
    float* __restrict__ C, int lda, int N, int Ktot)
{
    constexpr int NF = BN/16;
    constexpr int SB = BN + 8;       // 136 or 72; both ≡ 8 (mod 32)
    constexpr int BITER = BN/64;     // B-loader iterations (2 or 1)
    __shared__ float As[2][128*20];
    __shared__ float Bs[2][16*SB];

    const int tid  = threadIdx.x;
    const int warp = tid >> 5, lane = tid & 31;
    const int wr = warp & 3, wc = warp >> 2;
    const int g = lane >> 2, t = lane & 3;
    const int mw = wr * 32, nw = wc * (BN/2);

    const float* Ab = A  + (size_t)blockIdx.y*128*lda;
    const float* Bb = Bw + blockIdx.x*BN;

    const int ar0 = tid >> 2,       ac0 = (tid & 3) * 4;
    const int ar1 = (tid+256) >> 2, ac1 = ((tid+256) & 3) * 4;
    const int br  = tid / (BN/4),   bc  = (tid % (BN/4)) * 4;
    const int br2 = (tid+256) / (BN/4), bc2 = ((tid+256) % (BN/4)) * 4;

    float4 pa0, pa1, pb0, pb1;
    auto fetch = [&](int k0){
        pa0 = cvt4(*(const float4*)(Ab + (size_t)ar0*lda + k0 + ac0));
        pa1 = cvt4(*(const float4*)(Ab + (size_t)ar1*lda + k0 + ac1));
        pb0 = cvt4(*(const float4*)(Bb + (size_t)(k0+br)*N + bc));
        if (BITER == 2)
            pb1 = cvt4(*(const float4*)(Bb + (size_t)(k0+br2)*N + bc2));
    };
    auto stage = [&](int buf){
        *(float4*)(As[buf] + ar0*20 + ac0) = pa0;
        *(float4*)(As[buf] + ar1*20 + ac1) = pa1;
        *(float4*)(Bs[buf] + br*SB + bc) = pb0;
        if (BITER == 2) *(float4*)(Bs[buf] + br2*SB + bc2) = pb1;
    };

    float acc[2][NF][4] = {};

    fetch(0); stage(0);
    __syncthreads();

    const int niter = Ktot >> 4;
    for (int it = 0; it < niter; it++){
        const int cur = it & 1;
        if (it + 1 < niter) fetch((it+1) << 4);
        #pragma unroll
        for (int ks = 0; ks < 2; ks++){
            const int kk = ks * 8;
            u32 af[2][4];
            #pragma unroll
            for (int mf = 0; mf < 2; mf++){
                const int mb = mw + mf*16;
                af[mf][0] = __float_as_uint(As[cur][(mb+g)*20   + kk + t]);
                af[mf][1] = __float_as_uint(As[cur][(mb+8+g)*20 + kk + t]);
                af[mf][2] = __float_as_uint(As[cur][(mb+g)*20   + kk + 4 + t]);
                af[mf][3] = __float_as_uint(As[cur][(mb+8+g)*20 + kk + 4 + t]);
            }
            u32 bf[NF][2];
            #pragma unroll
            for (int nf = 0; nf < NF; nf++){
                const int nb = nw + nf*8;
                bf[nf][0] = __float_as_uint(Bs[cur][(kk+t)*SB   + nb + g]);
                bf[nf][1] = __float_as_uint(Bs[cur][(kk+4+t)*SB + nb + g]);
            }
            #pragma unroll
            for (int mf = 0; mf < 2; mf++)
                #pragma unroll
                for (int nf = 0; nf < NF; nf++)
                    mma8(acc[mf][nf], af[mf], bf[nf]);
        }
        if (it + 1 < niter){ stage(cur^1); __syncthreads(); }
    }

    const size_t row0 = (size_t)blockIdx.y*128 + wr*32;
    const int col0 = blockIdx.x*BN + wc*(BN/2);

    #pragma unroll
    for (int mf = 0; mf < 2; mf++){
        #pragma unroll
        for (int nf = 0; nf < NF; nf++){
            const int col = col0 + nf*8 + t*2;
            float b0 = 0.f, b1 = 0.f;
            if (EPI != 0){ b0 = bias[col]; b1 = bias[col+1]; }
            #pragma unroll
            for (int half = 0; half < 2; half++){
                const size_t r = row0 + mf*16 + g + half*8;
                float v0 = acc[mf][nf][half*2]   + b0;
                float v1 = acc[mf][nf][half*2+1] + b1;
                if (EPI == 1){
                    v0 = 0.5f*v0*(1.0f + erff(v0*0.70710678118654752f));
                    v1 = 0.5f*v1*(1.0f + erff(v1*0.70710678118654752f));
                }
                if (EPI == 2){
                    float2 rr = *(const float2*)(Res + r*(size_t)N + col);
                    v0 += rr.x; v1 += rr.y;
                }
                *(float2*)(C + r*(size_t)N + col) = make_float2(v0, v1);
            }
        }
    }
}

// =====================================================================
// Fused attention: per (b,h,q-tile of 64):
//   S = 0.125 * Q K^T (smem, 64x516), += bias (streamed from global),
//   softmax rows in smem, O = P V (double-buffered V tiles).
// smem: Qs 64x68 | KV 2x64x72 (>= K tile 128x68) | S 64x516  = 182KB dyn.
// =====================================================================
#define FA_SMEM_BYTES ((64*68 + 2*64*72 + 64*516) * 4)

__global__ void __launch_bounds__(256) fused_attn(
    const float* __restrict__ qkv, const float* __restrict__ bias,
    float* __restrict__ out)
{
    extern __shared__ float smem[];
    float* Qs  = smem;                   // [64][68]
    float* KVs = smem + 64*68;           // 9216 floats
    float* Ssm = smem + 64*68 + 9216;    // [64][516]

    const int tid  = threadIdx.x;
    const int warp = tid >> 5, lane = tid & 31;
    const int wr = warp >> 2, wc = warp & 3;   // 2 x 4 warp grid
    const int g = lane >> 2, t = lane & 3;
    const int z = blockIdx.y, b = z >> 3, h = z & 7;
    const int q0 = blockIdx.x * 64;

    const float* Qg = qkv + ((size_t)(b*KKK) + q0)*(3*DDD) + h*HDIM;
    const float* Kg = qkv + (size_t)(b*KKK)*(3*DDD) + DDD   + h*HDIM;
    const float* Vg = qkv + (size_t)(b*KKK)*(3*DDD) + 2*DDD + h*HDIM;
    const float* Bg = bias + ((size_t)z*KKK + q0)*KKK;

    // stage Q (64x64), tf32
    #pragma unroll
    for (int i = 0; i < 4; i++){
        const int idx = tid + i*256;
        const int r = idx >> 4, c = (idx & 15)*4;
        *(float4*)(Qs + r*68 + c) = cvt4(*(const float4*)(Qg + (size_t)r*(3*DDD) + c));
    }

    // ---- phase 1: S = 0.125 * Q K^T into Ssm ----
    #pragma unroll 1
    for (int kt = 0; kt < 4; kt++){
        if (kt) __syncthreads();          // protect KVs reuse
        #pragma unroll
        for (int i = 0; i < 8; i++){
            const int idx = tid + i*256;
            const int r = idx >> 4, c = (idx & 15)*4;
            *(float4*)(KVs + r*68 + c) =
                cvt4(*(const float4*)(Kg + (size_t)(kt*128 + r)*(3*DDD) + c));
        }
        __syncthreads();

        float sacc[2][4][4] = {};
        const int mw = wr*32, nw = wc*32;
        #pragma unroll
        for (int kk = 0; kk < 64; kk += 8){
            u32 af[2][4];
            #pragma unroll
            for (int mf = 0; mf < 2; mf++){
                const int mb = mw + mf*16;
                af[mf][0] = __float_as_uint(Qs[(mb+g)*68   + kk + t]);
                af[mf][1] = __float_as_uint(Qs[(mb+8+g)*68 + kk + t]);
                af[mf][2] = __float_as_uint(Qs[(mb+g)*68   + kk + 4 + t]);
                af[mf][3] = __float_as_uint(Qs[(mb+8+g)*68 + kk + 4 + t]);
            }
            u32 bf[4][2];
            #pragma unroll
            for (int nf = 0; nf < 4; nf++){
                const int nb = nw + nf*8;
                bf[nf][0] = __float_as_uint(KVs[(nb+g)*68 + kk + t]);
                bf[nf][1] = __float_as_uint(KVs[(nb+g)*68 + kk + 4 + t]);
            }
            #pragma unroll
            for (int mf = 0; mf < 2; mf++)
                #pragma unroll
                for (int nf = 0; nf < 4; nf++)
                    mma8(sacc[mf][nf], af[mf], bf[nf]);
        }
        #pragma unroll
        for (int mf = 0; mf < 2; mf++)
            #pragma unroll
            for (int nf = 0; nf < 4; nf++){
                const int col = kt*128 + nw + nf*8 + t*2;
                const int r0 = mw + mf*16 + g;
                *(float2*)(Ssm + r0*516 + col) =
                    make_float2(0.125f*sacc[mf][nf][0], 0.125f*sacc[mf][nf][1]);
                *(float2*)(Ssm + (r0+8)*516 + col) =
                    make_float2(0.125f*sacc[mf][nf][2], 0.125f*sacc[mf][nf][3]);
            }
    }
    __syncthreads();

    // ---- softmax over k (row = warp*8 + rr), bias streamed from global ----
    #pragma unroll 1
    for (int rr = 0; rr < 8; rr++){
        const int row = warp*8 + rr;
        float v[16];
        #pragma unroll
        for (int j = 0; j < 4; j++){
            float4 s4 = *(float4*)(Ssm + row*516 + lane*4 + j*128);
            float4 b4 = *(const float4*)(Bg + (size_t)row*KKK + lane*4 + j*128);
            v[j*4+0] = s4.x + b4.x; v[j*4+1] = s4.y + b4.y;
            v[j*4+2] = s4.z + b4.z; v[j*4+3] = s4.w + b4.w;
        }
        float m = v[0];
        #pragma unroll
        for (int i = 1; i < 16; i++) m = fmaxf(m, v[i]);
        #pragma unroll
        for (int o = 16; o > 0; o >>= 1) m = fmaxf(m, __shfl_xor_sync(0xffffffffu, m, o));
        float s = 0.f;
        #pragma unroll
        for (int i = 0; i < 16; i++){ v[i] = expf(v[i] - m); s += v[i]; }
        #pragma unroll
        for (int o = 16; o > 0; o >>= 1) s += __shfl_xor_sync(0xffffffffu, s, o);
        const float rinv = 1.0f/s;
        #pragma unroll
        for (int j = 0; j < 4; j++){
            float4 o4 = make_float4(to_tf32(v[j*4+0]*rinv), to_tf32(v[j*4+1]*rinv),
                                    to_tf32(v[j*4+2]*rinv), to_tf32(v[j*4+3]*rinv));
            *(float4*)(Ssm + row*516 + lane*4 + j*128) = o4;
        }
    }
    __syncthreads();

    // ---- phase 2: O = P V, double-buffered V tiles (64x64) ----
    float oacc[2][2][4] = {};
    float4 pv[4];
    auto fetchV = [&](int vt){
        #pragma unroll
        for (int i = 0; i < 4; i++){
            const int idx = tid + i*256;
            const int r = idx >> 4, c = (idx & 15)*4;
            pv[i] = cvt4(*(const float4*)(Vg + (size_t)(vt*64 + r)*(3*DDD) + c));
        }
    };
    auto stageV = [&](int buf){
        #pragma unroll
        for (int i = 0; i < 4; i++){
            const int idx = tid + i*256;
            const int r = idx >> 4, c = (idx & 15)*4;
            *(float4*)(KVs + buf*4608 + r*72 + c) = pv[i];
        }
    };
    fetchV(0); stageV(0);
    __syncthreads();

    #pragma unroll 1
    for (int vt = 0; vt < 8; vt++){
        const int cur = vt & 1;
        if (vt < 7) fetchV(vt+1);
        const float* Vb = KVs + cur*4608;
        const int mw = wr*32, nw2 = wc*16;
        #pragma unroll
        for (int kk = 0; kk < 64; kk += 8){
            const int kc = vt*64 + kk;
            u32 af[2][4];
            #pragma unroll
            for (int mf = 0; mf < 2; mf++){
                const int mb = mw + mf*16;
                af[mf][0] = __float_as_uint(Ssm[(mb+g)*516   + kc + t]);
                af[mf][1] = __float_as_uint(Ssm[(mb+8+g)*516 + kc + t]);
                af[mf][2] = __float_as_uint(Ssm[(mb+g)*516   + kc + 4 + t]);
                af[mf][3] = __float_as_uint(Ssm[(mb+8+g)*516 + kc + 4 + t]);
            }
            u32 bf[2][2];
            #pragma unroll
            for (int nf = 0; nf < 2; nf++){
                const int nb = nw2 + nf*8;
                bf[nf][0] = __float_as_uint(Vb[(kk+t)*72   + nb + g]);
                bf[nf][1] = __float_as_uint(Vb[(kk+4+t)*72 + nb + g]);
            }
            #pragma unroll
            for (int mf = 0; mf < 2; mf++)
                #pragma unroll
                for (int nf = 0; nf < 2; nf++)
                    mma8(oacc[mf][nf], af[mf], bf[nf]);
        }
        if (vt < 7){ stageV(cur^1); __syncthreads(); }
    }

    // epilogue: write O to attnout (B,K,D)
    float* Ob = out + ((size_t)(b*KKK) + q0)*DDD + h*HDIM;
    #pragma unroll
    for (int mf = 0; mf < 2; mf++)
        #pragma unroll
        for (int nf = 0; nf < 2; nf++){
            const int r0 = wr*32 + mf*16 + g;
            const int col = wc*16 + nf*8 + t*2;
            *(float2*)(Ob + (size_t)r0*DDD + col) =
                make_float2(oacc[mf][nf][0], oacc[mf][nf][1]);
            *(float2*)(Ob + (size_t)(r0+8)*DDD + col) =
                make_float2(oacc[mf][nf][2], oacc[mf][nf][3]);
        }
}

// ---------- LayerNorm: one block per row (512 elems) ----------
__global__ void __launch_bounds__(128) ln_kernel(
    const float* __restrict__ in, const float* __restrict__ w,
    const float* __restrict__ b, float* __restrict__ out)
{
    const int row = blockIdx.x;
    const int t = threadIdx.x;  // 128
    float4 v = ((const float4*)(in + (size_t)row*DDD))[t];
    float s  = v.x+v.y+v.z+v.w;
    float ss = v.x*v.x+v.y*v.y+v.z*v.z+v.w*v.w;
    #pragma unroll
    for (int o=16;o>0;o>>=1){
        s  += __shfl_xor_sync(0xffffffffu, s,  o);
        ss += __shfl_xor_sync(0xffffffffu, ss, o);
    }
    __shared__ float sm[8];
    const int wid = t>>5, lid = t&31;
    if (lid==0){ sm[wid]=s; sm[4+wid]=ss; }
    __syncthreads();
    s  = sm[0]+sm[1]+sm[2]+sm[3];
    ss = sm[4]+sm[5]+sm[6]+sm[7];
    const float mean = s*(1.0f/DDD);
    const float var  = ss*(1.0f/DDD) - mean*mean;
    const float inv  = rsqrtf(var + 1e-5f);
    float4 wv = ((const float4*)w)[t];
    float4 bv = ((const float4*)b)[t];
    float4 o4;
    o4.x = (v.x-mean)*inv*wv.x + bv.x;
    o4.y = (v.y-mean)*inv*wv.y + bv.y;
    o4.z = (v.z-mean)*inv*wv.z + bv.z;
    o4.w = (v.w-mean)*inv*wv.w + bv.w;
    ((float4*)(out + (size_t)row*DDD))[t] = o4;
}

// ---------- Edge bias (HBM-bound): logits = edge_b + pairwise @ edge_w ----------
__global__ void __launch_bounds__(128) edge_bias_kernel(
    const float* __restrict__ pw, const float* __restrict__ ew,
    const float* __restrict__ eb, float* __restrict__ logits)
{
    __shared__ float ews[DPP*NH];  // [d][h]
    const int q = blockIdx.x;
    const int b = blockIdx.y;
    const int tid = threadIdx.x;   // 128
    ((float4*)ews)[tid]       = ((const float4*)ew)[tid];
    ((float4*)ews)[tid + 128] = ((const float4*)ew)[tid + 128];
    __syncthreads();

    const int k0 = tid*4;
    const float* base = pw + (((size_t)b*KKK + q)*KKK + k0)*DPP;

    u64 acc[4][4];   // [k-sub][head-pair]
    #pragma unroll
    for (int j=0;j<4;j++){
        u64 ini = pack2f(eb[2*j], eb[2*j+1]);
        #pragma unroll
        for (int g=0;g<4;g++) acc[g][j] = ini;
    }

    #pragma unroll 4
    for (int d4=0; d4<32; d4++){
        float4 p[4];
        #pragma unroll
        for (int g=0;g<4;g++)
            p[g] = *(const float4*)(base + (size_t)g*DPP + d4*4);
        #pragma unroll
        for (int x=0;x<4;x++){
            const int d = d4*4 + x;
            const u64* e2 = (const u64*)&ews[d*NH];
            u64 e0=e2[0], e1=e2[1], e2v=e2[2], e3=e2[3];
            #pragma unroll
            for (int g=0;g<4;g++){
                const float pv = (x==0)?p[g].x : (x==1)?p[g].y : (x==2)?p[g].z : p[g].w;
                u64 pd = dup2f(pv);
                ffma2(acc[g][0], pd, e0);
                ffma2(acc[g][1], pd, e1);
                ffma2(acc[g][2], pd, e2v);
                ffma2(acc[g][3], pd, e3);
            }
        }
    }

    #pragma unroll
    for (int j=0;j<4;j++){
        float x0,y0,x1,y1,x2,y2,x3,y3;
        unpack2f(acc[0][j],x0,y0); unpack2f(acc[1][j],x1,y1);
        unpack2f(acc[2][j],x2,y2); unpack2f(acc[3][j],x3,y3);
        const size_t b0 = (((size_t)(b*NH + 2*j  )*KKK + q)*KKK) + k0;
        const size_t b1 = (((size_t)(b*NH + 2*j+1)*KKK + q)*KKK) + k0;
        *(float4*)(logits + b0) = make_float4(x0,x1,x2,x3);
        *(float4*)(logits + b1) = make_float4(y0,y1,y2,y3);
    }
}

// ---------- host launch ----------
extern "C" void kernel_launch(void* const* d_in, const int* in_sizes, int n_in,
                              void* d_out, int out_size)
{
    const float* slots    = (const float*)d_in[0];
    const float* pairwise = (const float*)d_in[1];
    const float* ln1w     = (const float*)d_in[2];
    const float* ln1b     = (const float*)d_in[3];
    const float* ln2w     = (const float*)d_in[4];
    const float* ln2b     = (const float*)d_in[5];
    const float* wqkv     = (const float*)d_in[6];
    const float* edge_w   = (const float*)d_in[7];
    const float* edge_b   = (const float*)d_in[8];
    const float* out_w    = (const float*)d_in[9];
    const float* out_b    = (const float*)d_in[10];
    const float* ffn_w1   = (const float*)d_in[11];
    const float* ffn_b1   = (const float*)d_in[12];
    const float* ffn_w2   = (const float*)d_in[13];
    const float* ffn_b2   = (const float*)d_in[14];
    float* out = (float*)d_out;

    float *x_, *qkv_, *log_, *ao_, *s2_, *ffn_;
    cudaGetSymbolAddress((void**)&x_,   g_x);
    cudaGetSymbolAddress((void**)&qkv_, g_qkv);
    cudaGetSymbolAddress((void**)&log_, g_logits);
    cudaGetSymbolAddress((void**)&ao_,  g_attnout);
    cudaGetSymbolAddress((void**)&s2_,  g_slots2);
    cudaGetSymbolAddress((void**)&ffn_, g_ffn);

    cudaFuncSetAttribute(fused_attn,
        cudaFuncAttributeMaxDynamicSharedMemorySize, FA_SMEM_BYTES);

    // 1) LN1
    ln_kernel<<<MROWS,128>>>(slots, ln1w, ln1b, x_);
    // 2) QKV projection (2048 x 1536 x 512), tf32 tensor cores
    mma_proj<128,0><<<dim3(3*DDD/128, MROWS/128), 256>>>(
        x_, wqkv, nullptr, nullptr, qkv_, DDD, 3*DDD, DDD);
    // 3) edge bias -> logits buffer
    edge_bias_kernel<<<dim3(KKK,BB),128>>>(pairwise, edge_w, edge_b, log_);
    // 4-6) fused: S = 0.125*QK^T + bias, softmax, P@V -> attnout
    fused_attn<<<dim3(KKK/64, BH), 256, FA_SMEM_BYTES>>>(qkv_, log_, ao_);
    // 7) out projection + residual (2048 x 512 x 512)
    mma_proj<64,2><<<dim3(DDD/64, MROWS/128), 256>>>(
        ao_, out_w, out_b, slots, s2_, DDD, DDD, DDD);
    // 8) LN2
    ln_kernel<<<MROWS,128>>>(s2_, ln2w, ln2b, x_);
    // 9) FFN1 + exact GELU (2048 x 2048 x 512)
    mma_proj<128,1><<<dim3(4*DDD/128, MROWS/128), 256>>>(
        x_, ffn_w1, ffn_b1, nullptr, ffn_, DDD, 4*DDD, DDD);
    // 10) FFN2 + residual (2048 x 512 x 2048) -> final output
    mma_proj<64,2><<<dim3(DDD/64, MROWS/128), 256>>>(
        ffn_, ffn_w2, ffn_b2, s2_, out, 4*DDD, DDD, 4*DDD);
}

// round 17
// speedup vs baseline: 1.0777x; 1.0006x over previous
#include <cuda_runtime.h>
#include <math.h>

// Problem constants
#define BB 4
#define KKK 512          // slots per batch
#define DDD 512          // slot dim
#define DPP 128          // pairwise dim
#define NH 8             // heads
#define HDIM 64          // head dim
#define MROWS (BB*KKK)   // 2048
#define BH (BB*NH)       // 32

typedef unsigned u32;
typedef unsigned long long u64;

// ---------- packed fp32x2 helpers (edge bias kernel) ----------
__device__ __forceinline__ u64 dup2f(float x){
    u64 r; unsigned xi = __float_as_uint(x);
    asm("mov.b64 %0, {%1,%1};" : "=l"(r) : "r"(xi));
    return r;
}
__device__ __forceinline__ u64 pack2f(float x, float y){
    u64 r;
    asm("mov.b64 %0, {%1,%2};" : "=l"(r) : "r"(__float_as_uint(x)), "r"(__float_as_uint(y)));
    return r;
}
__device__ __forceinline__ void unpack2f(u64 v, float &x, float &y){
    unsigned a,b;
    asm("mov.b64 {%0,%1}, %2;" : "=r"(a), "=r"(b) : "l"(v));
    x = __uint_as_float(a); y = __uint_as_float(b);
}
__device__ __forceinline__ void ffma2(u64 &d, u64 a, u64 b){
    asm("fma.rn.f32x2 %0, %1, %2, %0;" : "+l"(d) : "l"(a), "l"(b));
}

// ---------- tf32 MMA helpers ----------
__device__ __forceinline__ float to_tf32(float x){
    float r; asm("cvt.rna.tf32.f32 %0, %1;" : "=f"(r) : "f"(x)); return r;
}
__device__ __forceinline__ float4 cvt4(float4 v){
    v.x = to_tf32(v.x); v.y = to_tf32(v.y);
    v.z = to_tf32(v.z); v.w = to_tf32(v.w);
    return v;
}
__device__ __forceinline__ void mma8(float* c, const u32* a, const u32* b){
    asm("mma.sync.aligned.m16n8k8.row.col.f32.tf32.tf32.f32 "
        "{%0,%1,%2,%3}, {%4,%5,%6,%7}, {%8,%9}, {%0,%1,%2,%3};"
        : "+f"(c[0]), "+f"(c[1]), "+f"(c[2]), "+f"(c[3])
        : "r"(a[0]), "r"(a[1]), "r"(a[2]), "r"(a[3]),
          "r"(b[0]), "r"(b[1]));
}

// ---------- scratch (no dynamic allocation allowed) ----------
__device__ float g_x[MROWS*DDD];
__device__ float g_qkv[MROWS*3*DDD];
__device__ float g_logits[(size_t)BH*KKK*KKK];   // edge bias buffer (33.5 MB)
__device__ float g_attnout[MROWS*DDD];
__device__ float g_slots2[MROWS*DDD];
__device__ float g_ffn[MROWS*4*DDD];

// =====================================================================
// mma_proj: C(128 x BN per block) = A(M x Ktot) @ B(Ktot x N), tf32 MMA,
// double-buffered smem (ONE __syncthreads per k16 tile).
// EPI: 0 = none, 1 = +bias then exact GELU, 2 = +bias then +residual
// =====================================================================
template<int BN, int EPI>
__global__ void __launch_bounds__(256) mma_proj(
    const float* __restrict__ A, const float* __restrict__ Bw,
    const float* __restrict__ bias, const float* __restrict__ Res,
    float* __restrict__ C, int lda, int N, int Ktot)
{
    constexpr int NF = BN/16;
    constexpr int SB = BN + 8;       // 136 or 72; both ≡ 8 (mod 32)
    constexpr int BITER = BN/64;     // B-loader iterations (2 or 1)
    __shared__ float As[2][128*20];
    __shared__ float Bs[2][16*SB];

    const int tid  = threadIdx.x;
    const int warp = tid >> 5, lane = tid & 31;
    const int wr = warp & 3, wc = warp >> 2;
    const int g = lane >> 2, t = lane & 3;
    const int mw = wr * 32, nw = wc * (BN/2);

    const float* Ab = A  + (size_t)blockIdx.y*128*lda;
    const float* Bb = Bw + blockIdx.x*BN;

    const int ar0 = tid >> 2,       ac0 = (tid & 3) * 4;
    const int ar1 = (tid+256) >> 2, ac1 = ((tid+256) & 3) * 4;
    const int br  = tid / (BN/4),   bc  = (tid % (BN/4)) * 4;
    const int br2 = (tid+256) / (BN/4), bc2 = ((tid+256) % (BN/4)) * 4;

    float4 pa0, pa1, pb0, pb1;
    auto fetch = [&](int k0){
        pa0 = cvt4(*(const float4*)(Ab + (size_t)ar0*lda + k0 + ac0));
        pa1 = cvt4(*(const float4*)(Ab + (size_t)ar1*lda + k0 + ac1));
        pb0 = cvt4(*(const float4*)(Bb + (size_t)(k0+br)*N + bc));
        if (BITER == 2)
            pb1 = cvt4(*(const float4*)(Bb + (size_t)(k0+br2)*N + bc2));
    };
    auto stage = [&](int buf){
        *(float4*)(As[buf] + ar0*20 + ac0) = pa0;
        *(float4*)(As[buf] + ar1*20 + ac1) = pa1;
        *(float4*)(Bs[buf] + br*SB + bc) = pb0;
        if (BITER == 2) *(float4*)(Bs[buf] + br2*SB + bc2) = pb1;
    };

    float acc[2][NF][4] = {};

    fetch(0); stage(0);
    __syncthreads();

    const int niter = Ktot >> 4;
    for (int it = 0; it < niter; it++){
        const int cur = it & 1;
        if (it + 1 < niter) fetch((it+1) << 4);
        #pragma unroll
        for (int ks = 0; ks < 2; ks++){
            const int kk = ks * 8;
            u32 af[2][4];
            #pragma unroll
            for (int mf = 0; mf < 2; mf++){
                const int mb = mw + mf*16;
                af[mf][0] = __float_as_uint(As[cur][(mb+g)*20   + kk + t]);
                af[mf][1] = __float_as_uint(As[cur][(mb+8+g)*20 + kk + t]);
                af[mf][2] = __float_as_uint(As[cur][(mb+g)*20   + kk + 4 + t]);
                af[mf][3] = __float_as_uint(As[cur][(mb+8+g)*20 + kk + 4 + t]);
            }
            u32 bf[NF][2];
            #pragma unroll
            for (int nf = 0; nf < NF; nf++){
                const int nb = nw + nf*8;
                bf[nf][0] = __float_as_uint(Bs[cur][(kk+t)*SB   + nb + g]);
                bf[nf][1] = __float_as_uint(Bs[cur][(kk+4+t)*SB + nb + g]);
            }
            #pragma unroll
            for (int mf = 0; mf < 2; mf++)
                #pragma unroll
                for (int nf = 0; nf < NF; nf++)
                    mma8(acc[mf][nf], af[mf], bf[nf]);
        }
        if (it + 1 < niter){ stage(cur^1); __syncthreads(); }
    }

    const size_t row0 = (size_t)blockIdx.y*128 + wr*32;
    const int col0 = blockIdx.x*BN + wc*(BN/2);

    #pragma unroll
    for (int mf = 0; mf < 2; mf++){
        #pragma unroll
        for (int nf = 0; nf < NF; nf++){
            const int col = col0 + nf*8 + t*2;
            float b0 = 0.f, b1 = 0.f;
            if (EPI != 0){ b0 = bias[col]; b1 = bias[col+1]; }
            #pragma unroll
            for (int half = 0; half < 2; half++){
                const size_t r = row0 + mf*16 + g + half*8;
                float v0 = acc[mf][nf][half*2]   + b0;
                float v1 = acc[mf][nf][half*2+1] + b1;
                if (EPI == 1){
                    v0 = 0.5f*v0*(1.0f + erff(v0*0.70710678118654752f));
                    v1 = 0.5f*v1*(1.0f + erff(v1*0.70710678118654752f));
                }
                if (EPI == 2){
                    float2 rr = *(const float2*)(Res + r*(size_t)N + col);
                    v0 += rr.x; v1 += rr.y;
                }
                *(float2*)(C + r*(size_t)N + col) = make_float2(v0, v1);
            }
        }
    }
}

// =====================================================================
// Fused attention: per (b,h,q-tile of 64):
//   S = 0.125 * Q K^T (smem, 64x516), += bias (streamed from global),
//   softmax rows in smem, O = P V (double-buffered V tiles).
// smem: Qs 64x68 | KV 2x64x72 (>= K tile 128x68) | S 64x516  = 182KB dyn.
// =====================================================================
#define FA_SMEM_BYTES ((64*68 + 2*64*72 + 64*516) * 4)

__global__ void __launch_bounds__(256) fused_attn(
    const float* __restrict__ qkv, const float* __restrict__ bias,
    float* __restrict__ out)
{
    extern __shared__ float smem[];
    float* Qs  = smem;                   // [64][68]
    float* KVs = smem + 64*68;           // 9216 floats
    float* Ssm = smem + 64*68 + 9216;    // [64][516]

    const int tid  = threadIdx.x;
    const int warp = tid >> 5, lane = tid & 31;
    const int wr = warp >> 2, wc = warp & 3;   // 2 x 4 warp grid
    const int g = lane >> 2, t = lane & 3;
    const int z = blockIdx.y, b = z >> 3, h = z & 7;
    const int q0 = blockIdx.x * 64;

    const float* Qg = qkv + ((size_t)(b*KKK) + q0)*(3*DDD) + h*HDIM;
    const float* Kg = qkv + (size_t)(b*KKK)*(3*DDD) + DDD   + h*HDIM;
    const float* Vg = qkv + (size_t)(b*KKK)*(3*DDD) + 2*DDD + h*HDIM;
    const float* Bg = bias + ((size_t)z*KKK + q0)*KKK;

    // stage Q (64x64), tf32
    #pragma unroll
    for (int i = 0; i < 4; i++){
        const int idx = tid + i*256;
        const int r = idx >> 4, c = (idx & 15)*4;
        *(float4*)(Qs + r*68 + c) = cvt4(*(const float4*)(Qg + (size_t)r*(3*DDD) + c));
    }

    // ---- phase 1: S = 0.125 * Q K^T into Ssm ----
    #pragma unroll 1
    for (int kt = 0; kt < 4; kt++){
        if (kt) __syncthreads();          // protect KVs reuse
        #pragma unroll
        for (int i = 0; i < 8; i++){
            const int idx = tid + i*256;
            const int r = idx >> 4, c = (idx & 15)*4;
            *(float4*)(KVs + r*68 + c) =
                cvt4(*(const float4*)(Kg + (size_t)(kt*128 + r)*(3*DDD) + c));
        }
        __syncthreads();

        float sacc[2][4][4] = {};
        const int mw = wr*32, nw = wc*32;
        #pragma unroll
        for (int kk = 0; kk < 64; kk += 8){
            u32 af[2][4];
            #pragma unroll
            for (int mf = 0; mf < 2; mf++){
                const int mb = mw + mf*16;
                af[mf][0] = __float_as_uint(Qs[(mb+g)*68   + kk + t]);
                af[mf][1] = __float_as_uint(Qs[(mb+8+g)*68 + kk + t]);
                af[mf][2] = __float_as_uint(Qs[(mb+g)*68   + kk + 4 + t]);
                af[mf][3] = __float_as_uint(Qs[(mb+8+g)*68 + kk + 4 + t]);
            }
            u32 bf[4][2];
            #pragma unroll
            for (int nf = 0; nf < 4; nf++){
                const int nb = nw + nf*8;
                bf[nf][0] = __float_as_uint(KVs[(nb+g)*68 + kk + t]);
                bf[nf][1] = __float_as_uint(KVs[(nb+g)*68 + kk + 4 + t]);
            }
            #pragma unroll
            for (int mf = 0; mf < 2; mf++)
                #pragma unroll
                for (int nf = 0; nf < 4; nf++)
                    mma8(sacc[mf][nf], af[mf], bf[nf]);
        }
        #pragma unroll
        for (int mf = 0; mf < 2; mf++)
            #pragma unroll
            for (int nf = 0; nf < 4; nf++){
                const int col = kt*128 + nw + nf*8 + t*2;
                const int r0 = mw + mf*16 + g;
                *(float2*)(Ssm + r0*516 + col) =
                    make_float2(0.125f*sacc[mf][nf][0], 0.125f*sacc[mf][nf][1]);
                *(float2*)(Ssm + (r0+8)*516 + col) =
                    make_float2(0.125f*sacc[mf][nf][2], 0.125f*sacc[mf][nf][3]);
            }
    }
    __syncthreads();

    // ---- softmax over k (row = warp*8 + rr), bias streamed from global ----
    #pragma unroll 1
    for (int rr = 0; rr < 8; rr++){
        const int row = warp*8 + rr;
        float v[16];
        #pragma unroll
        for (int j = 0; j < 4; j++){
            float4 s4 = *(float4*)(Ssm + row*516 + lane*4 + j*128);
            float4 b4 = *(const float4*)(Bg + (size_t)row*KKK + lane*4 + j*128);
            v[j*4+0] = s4.x + b4.x; v[j*4+1] = s4.y + b4.y;
            v[j*4+2] = s4.z + b4.z; v[j*4+3] = s4.w + b4.w;
        }
        float m = v[0];
        #pragma unroll
        for (int i = 1; i < 16; i++) m = fmaxf(m, v[i]);
        #pragma unroll
        for (int o = 16; o > 0; o >>= 1) m = fmaxf(m, __shfl_xor_sync(0xffffffffu, m, o));
        float s = 0.f;
        #pragma unroll
        for (int i = 0; i < 16; i++){ v[i] = expf(v[i] - m); s += v[i]; }
        #pragma unroll
        for (int o = 16; o > 0; o >>= 1) s += __shfl_xor_sync(0xffffffffu, s, o);
        const float rinv = 1.0f/s;
        #pragma unroll
        for (int j = 0; j < 4; j++){
            float4 o4 = make_float4(to_tf32(v[j*4+0]*rinv), to_tf32(v[j*4+1]*rinv),
                                    to_tf32(v[j*4+2]*rinv), to_tf32(v[j*4+3]*rinv));
            *(float4*)(Ssm + row*516 + lane*4 + j*128) = o4;
        }
    }
    __syncthreads();

    // ---- phase 2: O = P V, double-buffered V tiles (64x64) ----
    float oacc[2][2][4] = {};
    float4 pv[4];
    auto fetchV = [&](int vt){
        #pragma unroll
        for (int i = 0; i < 4; i++){
            const int idx = tid + i*256;
            const int r = idx >> 4, c = (idx & 15)*4;
            pv[i] = cvt4(*(const float4*)(Vg + (size_t)(vt*64 + r)*(3*DDD) + c));
        }
    };
    auto stageV = [&](int buf){
        #pragma unroll
        for (int i = 0; i < 4; i++){
            const int idx = tid + i*256;
            const int r = idx >> 4, c = (idx & 15)*4;
            *(float4*)(KVs + buf*4608 + r*72 + c) = pv[i];
        }
    };
    fetchV(0); stageV(0);
    __syncthreads();

    #pragma unroll 1
    for (int vt = 0; vt < 8; vt++){
        const int cur = vt & 1;
        if (vt < 7) fetchV(vt+1);
        const float* Vb = KVs + cur*4608;
        const int mw = wr*32, nw2 = wc*16;
        #pragma unroll
        for (int kk = 0; kk < 64; kk += 8){
            const int kc = vt*64 + kk;
            u32 af[2][4];
            #pragma unroll
            for (int mf = 0; mf < 2; mf++){
                const int mb = mw + mf*16;
                af[mf][0] = __float_as_uint(Ssm[(mb+g)*516   + kc + t]);
                af[mf][1] = __float_as_uint(Ssm[(mb+8+g)*516 + kc + t]);
                af[mf][2] = __float_as_uint(Ssm[(mb+g)*516   + kc + 4 + t]);
                af[mf][3] = __float_as_uint(Ssm[(mb+8+g)*516 + kc + 4 + t]);
            }
            u32 bf[2][2];
            #pragma unroll
            for (int nf = 0; nf < 2; nf++){
                const int nb = nw2 + nf*8;
                bf[nf][0] = __float_as_uint(Vb[(kk+t)*72   + nb + g]);
                bf[nf][1] = __float_as_uint(Vb[(kk+4+t)*72 + nb + g]);
            }
            #pragma unroll
            for (int mf = 0; mf < 2; mf++)
                #pragma unroll
                for (int nf = 0; nf < 2; nf++)
                    mma8(oacc[mf][nf], af[mf], bf[nf]);
        }
        if (vt < 7){ stageV(cur^1); __syncthreads(); }
    }

    // epilogue: write O to attnout (B,K,D)
    float* Ob = out + ((size_t)(b*KKK) + q0)*DDD + h*HDIM;
    #pragma unroll
    for (int mf = 0; mf < 2; mf++)
        #pragma unroll
        for (int nf = 0; nf < 2; nf++){
            const int r0 = wr*32 + mf*16 + g;
            const int col = wc*16 + nf*8 + t*2;
            *(float2*)(Ob + (size_t)r0*DDD + col) =
                make_float2(oacc[mf][nf][0], oacc[mf][nf][1]);
            *(float2*)(Ob + (size_t)(r0+8)*DDD + col) =
                make_float2(oacc[mf][nf][2], oacc[mf][nf][3]);
        }
}

// ---------- LayerNorm: one block per row (512 elems) ----------
__global__ void __launch_bounds__(128) ln_kernel(
    const float* __restrict__ in, const float* __restrict__ w,
    const float* __restrict__ b, float* __restrict__ out)
{
    const int row = blockIdx.x;
    const int t = threadIdx.x;  // 128
    float4 v = ((const float4*)(in + (size_t)row*DDD))[t];
    float s  = v.x+v.y+v.z+v.w;
    float ss = v.x*v.x+v.y*v.y+v.z*v.z+v.w*v.w;
    #pragma unroll
    for (int o=16;o>0;o>>=1){
        s  += __shfl_xor_sync(0xffffffffu, s,  o);
        ss += __shfl_xor_sync(0xffffffffu, ss, o);
    }
    __shared__ float sm[8];
    const int wid = t>>5, lid = t&31;
    if (lid==0){ sm[wid]=s; sm[4+wid]=ss; }
    __syncthreads();
    s  = sm[0]+sm[1]+sm[2]+sm[3];
    ss = sm[4]+sm[5]+sm[6]+sm[7];
    const float mean = s*(1.0f/DDD);
    const float var  = ss*(1.0f/DDD) - mean*mean;
    const float inv  = rsqrtf(var + 1e-5f);
    float4 wv = ((const float4*)w)[t];
    float4 bv = ((const float4*)b)[t];
    float4 o4;
    o4.x = (v.x-mean)*inv*wv.x + bv.x;
    o4.y = (v.y-mean)*inv*wv.y + bv.y;
    o4.z = (v.z-mean)*inv*wv.z + bv.z;
    o4.w = (v.w-mean)*inv*wv.w + bv.w;
    ((float4*)(out + (size_t)row*DDD))[t] = o4;
}

// ---------- Edge bias (HBM-bound): logits = edge_b + pairwise @ edge_w ----------
__global__ void __launch_bounds__(128) edge_bias_kernel(
    const float* __restrict__ pw, const float* __restrict__ ew,
    const float* __restrict__ eb, float* __restrict__ logits)
{
    __shared__ float ews[DPP*NH];  // [d][h]
    const int q = blockIdx.x;
    const int b = blockIdx.y;
    const int tid = threadIdx.x;   // 128
    ((float4*)ews)[tid]       = ((const float4*)ew)[tid];
    ((float4*)ews)[tid + 128] = ((const float4*)ew)[tid + 128];
    __syncthreads();

    const int k0 = tid*4;
    const float* base = pw + (((size_t)b*KKK + q)*KKK + k0)*DPP;

    u64 acc[4][4];   // [k-sub][head-pair]
    #pragma unroll
    for (int j=0;j<4;j++){
        u64 ini = pack2f(eb[2*j], eb[2*j+1]);
        #pragma unroll
        for (int g=0;g<4;g++) acc[g][j] = ini;
    }

    #pragma unroll 4
    for (int d4=0; d4<32; d4++){
        float4 p[4];
        #pragma unroll
        for (int g=0;g<4;g++)
            p[g] = *(const float4*)(base + (size_t)g*DPP + d4*4);
        #pragma unroll
        for (int x=0;x<4;x++){
            const int d = d4*4 + x;
            const u64* e2 = (const u64*)&ews[d*NH];
            u64 e0=e2[0], e1=e2[1], e2v=e2[2], e3=e2[3];
            #pragma unroll
            for (int g=0;g<4;g++){
                const float pv = (x==0)?p[g].x : (x==1)?p[g].y : (x==2)?p[g].z : p[g].w;
                u64 pd = dup2f(pv);
                ffma2(acc[g][0], pd, e0);
                ffma2(acc[g][1], pd, e1);
                ffma2(acc[g][2], pd, e2v);
                ffma2(acc[g][3], pd, e3);
            }
        }
    }

    #pragma unroll
    for (int j=0;j<4;j++){
        float x0,y0,x1,y1,x2,y2,x3,y3;
        unpack2f(acc[0][j],x0,y0); unpack2f(acc[1][j],x1,y1);
        unpack2f(acc[2][j],x2,y2); unpack2f(acc[3][j],x3,y3);
        const size_t b0 = (((size_t)(b*NH + 2*j  )*KKK + q)*KKK) + k0;
        const size_t b1 = (((size_t)(b*NH + 2*j+1)*KKK + q)*KKK) + k0;
        *(float4*)(logits + b0) = make_float4(x0,x1,x2,x3);
        *(float4*)(logits + b1) = make_float4(y0,y1,y2,y3);
    }
}

// ---------- host launch ----------
extern "C" void kernel_launch(void* const* d_in, const int* in_sizes, int n_in,
                              void* d_out, int out_size)
{
    const float* slots    = (const float*)d_in[0];
    const float* pairwise = (const float*)d_in[1];
    const float* ln1w     = (const float*)d_in[2];
    const float* ln1b     = (const float*)d_in[3];
    const float* ln2w     = (const float*)d_in[4];
    const float* ln2b     = (const float*)d_in[5];
    const float* wqkv     = (const float*)d_in[6];
    const float* edge_w   = (const float*)d_in[7];
    const float* edge_b   = (const float*)d_in[8];
    const float* out_w    = (const float*)d_in[9];
    const float* out_b    = (const float*)d_in[10];
    const float* ffn_w1   = (const float*)d_in[11];
    const float* ffn_b1   = (const float*)d_in[12];
    const float* ffn_w2   = (const float*)d_in[13];
    const float* ffn_b2   = (const float*)d_in[14];
    float* out = (float*)d_out;

    float *x_, *qkv_, *log_, *ao_, *s2_, *ffn_;
    cudaGetSymbolAddress((void**)&x_,   g_x);
    cudaGetSymbolAddress((void**)&qkv_, g_qkv);
    cudaGetSymbolAddress((void**)&log_, g_logits);
    cudaGetSymbolAddress((void**)&ao_,  g_attnout);
    cudaGetSymbolAddress((void**)&s2_,  g_slots2);
    cudaGetSymbolAddress((void**)&ffn_, g_ffn);

    cudaFuncSetAttribute(fused_attn,
        cudaFuncAttributeMaxDynamicSharedMemorySize, FA_SMEM_BYTES);

    // 1) LN1
    ln_kernel<<<MROWS,128>>>(slots, ln1w, ln1b, x_);
    // 2) QKV projection (2048 x 1536 x 512), tf32 tensor cores
    mma_proj<128,0><<<dim3(3*DDD/128, MROWS/128), 256>>>(
        x_, wqkv, nullptr, nullptr, qkv_, DDD, 3*DDD, DDD);
    // 3) edge bias -> logits buffer
    edge_bias_kernel<<<dim3(KKK,BB),128>>>(pairwise, edge_w, edge_b, log_);
    // 4-6) fused: S = 0.125*QK^T + bias, softmax, P@V -> attnout
    fused_attn<<<dim3(KKK/64, BH), 256, FA_SMEM_BYTES>>>(qkv_, log_, ao_);
    // 7) out projection + residual (2048 x 512 x 512)
    mma_proj<64,2><<<dim3(DDD/64, MROWS/128), 256>>>(
        ao_, out_w, out_b, slots, s2_, DDD, DDD, DDD);
    // 8) LN2
    ln_kernel<<<MROWS,128>>>(s2_, ln2w, ln2b, x_);
    // 9) FFN1 + exact GELU (2048 x 2048 x 512)
    mma_proj<128,1><<<dim3(4*DDD/128, MROWS/128), 256>>>(
        x_, ffn_w1, ffn_b1, nullptr, ffn_, DDD, 4*DDD, DDD);
    // 10) FFN2 + residual (2048 x 512 x 2048) -> final output
    mma_proj<64,2><<<dim3(DDD/64, MROWS/128), 256>>>(
        ffn_, ffn_w2, ffn_b2, s2_, out, 4*DDD, DDD, 4*DDD);
}